// round 7
// baseline (speedup 1.0000x reference)
#include <cuda_runtime.h>
#include <cuda_bf16.h>
#include <cstdint>
#include <math.h>

// Problem constants (KGramMLPSeqModel: T=1024, B=4, V=32000, E=1024, K=3, H=2048)
#define T_N   1024
#define B_N   4
#define V_N   32000
#define E_N   1024
#define KCTX  3
#define H_N   2048
#define M_N   (T_N * B_N)      // 4096
#define K1_N  (KCTX * E_N)     // 3072

// ---------------------------------------------------------------------------
// Device scratch (__device__ globals per allocation-free rule)
// ---------------------------------------------------------------------------
__device__ __nv_bfloat16 g_hh[(size_t)M_N * H_N];    // h hi   (M,H) K-major
__device__ __nv_bfloat16 g_hl[(size_t)M_N * H_N];    // h lo
__device__ __nv_bfloat16 g_wh[(size_t)V_N * H_N];    // Wout^T hi (V,H) K-major
__device__ __nv_bfloat16 g_wl[(size_t)V_N * H_N];    // Wout^T lo
__device__ __nv_bfloat16 g_eh[(size_t)V_N * E_N];    // embedding hi (V,E)
__device__ __nv_bfloat16 g_el[(size_t)V_N * E_N];    // embedding lo
__device__ __nv_bfloat16 g_w1h[(size_t)H_N * K1_N];  // W1^T hi (H,K1) K-major
__device__ __nv_bfloat16 g_w1l[(size_t)H_N * K1_N];  // W1^T lo

// ---------------------------------------------------------------------------
// Helpers (baseline PTX only: plain compute_103 target)
// ---------------------------------------------------------------------------
__device__ __forceinline__ uint32_t smem_u32(const void* p) {
    uint32_t a;
    asm("{ .reg .u64 t; cvta.to.shared.u64 t, %1; cvt.u32.u64 %0, t; }" : "=r"(a) : "l"(p));
    return a;
}
#define CP16(dst, src) \
    asm volatile("cp.async.cg.shared.global [%0], [%1], 16;" :: "r"(dst), "l"(src) : "memory")
#define CP_COMMIT() asm volatile("cp.async.commit_group;" ::: "memory")
#define CP_WAIT0()  asm volatile("cp.async.wait_group 0;" ::: "memory")

#define LDSM4(r, addr) \
    asm volatile("ldmatrix.sync.aligned.m8n8.x4.shared.b16 {%0,%1,%2,%3}, [%4];" \
        : "=r"((r)[0]), "=r"((r)[1]), "=r"((r)[2]), "=r"((r)[3]) : "r"(addr))

#define MMA16816(d, a, b0, b1) \
    asm volatile("mma.sync.aligned.m16n8k16.row.col.f32.bf16.bf16.f32 " \
        "{%0,%1,%2,%3}, {%4,%5,%6,%7}, {%8,%9}, {%0,%1,%2,%3};" \
        : "+f"((d)[0]), "+f"((d)[1]), "+f"((d)[2]), "+f"((d)[3]) \
        : "r"((a)[0]), "r"((a)[1]), "r"((a)[2]), "r"((a)[3]), "r"(b0), "r"(b1))

__device__ __forceinline__ void split_bf16(float v, __nv_bfloat16& hi, __nv_bfloat16& lo) {
    hi = __float2bfloat16(v);
    lo = __float2bfloat16(v - __bfloat162float(hi));
}

// ---------------------------------------------------------------------------
// Prepass A: elementwise split (embedding): fp32 -> bf16 hi/lo, same layout
// ---------------------------------------------------------------------------
__global__ __launch_bounds__(256)
void emb_split(const float* __restrict__ emb)
{
    const size_t i4 = ((size_t)blockIdx.x * 256 + threadIdx.x) * 4;
    const float4 v = *reinterpret_cast<const float4*>(emb + i4);
    __nv_bfloat16 h0, l0, h1, l1, h2, l2, h3, l3;
    split_bf16(v.x, h0, l0); split_bf16(v.y, h1, l1);
    split_bf16(v.z, h2, l2); split_bf16(v.w, h3, l3);
    __nv_bfloat162* oh = reinterpret_cast<__nv_bfloat162*>(g_eh + i4);
    __nv_bfloat162* ol = reinterpret_cast<__nv_bfloat162*>(g_el + i4);
    oh[0] = __nv_bfloat162(h0, h1); oh[1] = __nv_bfloat162(h2, h3);
    ol[0] = __nv_bfloat162(l0, l1); ol[1] = __nv_bfloat162(l2, l3);
}

// ---------------------------------------------------------------------------
// Prepass B: transpose + split: in (R, C) fp32 -> out (C, R) bf16 hi/lo
// ---------------------------------------------------------------------------
__global__ __launch_bounds__(256)
void split_transpose(const float* __restrict__ in,
                     __nv_bfloat16* __restrict__ oh,
                     __nv_bfloat16* __restrict__ ol,
                     int R, int C)
{
    __shared__ float tile[32][33];
    const int tx = threadIdx.x & 31;
    const int ty = threadIdx.x >> 5;          // 0..7
    const int cBase = blockIdx.x * 32;
    const int rBase = blockIdx.y * 32;

    #pragma unroll
    for (int j = 0; j < 4; j++)
        tile[ty + j * 8][tx] = in[(size_t)(rBase + ty + j * 8) * C + cBase + tx];
    __syncthreads();
    #pragma unroll
    for (int j = 0; j < 4; j++) {
        const int n = cBase + ty + j * 8;
        const int k = rBase + tx;
        __nv_bfloat16 hi, lo;
        split_bf16(tile[tx][ty + j * 8], hi, lo);
        oh[(size_t)n * R + k] = hi;
        ol[(size_t)n * R + k] = lo;
    }
}

// ---------------------------------------------------------------------------
// Shared GEMM geometry (both GEMMs):
//   BM=256, BN=256, BK=32; 16 warps (4M x 4N), warp tile 64x64; 512 threads.
//   ROWB=80 (64B data + 16B pad) -> conflict-free ldmatrix phases.
//   2-stage cp.async pipeline: wait -> sync -> issue next loads -> compute.
// ---------------------------------------------------------------------------
#define ROWB      80
#define A_BYTES   (256 * ROWB)     // 20480
#define B_BYTES   (256 * ROWB)     // 20480
#define OFF_AH    0
#define OFF_AL    A_BYTES
#define OFF_BH    (2 * A_BYTES)
#define OFF_BL    (2 * A_BYTES + B_BYTES)
#define STAGE_B   (2 * A_BYTES + 2 * B_BYTES)   // 81920
#define GEMM_SMEM (2 * STAGE_B)                 // 163840

// Compute one 32-k chunk for warp tile 64x64 (acc[4][8][4]); 3-product split.
#define COMPUTE_CHUNK(stb)                                                          \
    do {                                                                            \
        _Pragma("unroll")                                                           \
        for (int kk = 0; kk < 2; kk++) {                                            \
            const uint32_t colb = cselB + kk * 32;                                  \
            uint32_t ah[4][4], al[4][4];                                            \
            _Pragma("unroll")                                                       \
            for (int im = 0; im < 4; im++) {                                        \
                const uint32_t a = (stb) + OFF_AH + (wm * 64 + im * 16 + rsel) * ROWB + colb; \
                LDSM4(ah[im], a);                                                   \
                LDSM4(al[im], a + (OFF_AL - OFF_AH));                               \
            }                                                                       \
            uint32_t bh[4][4], bl[4][4];                                            \
            _Pragma("unroll")                                                       \
            for (int in = 0; in < 4; in++) {                                        \
                const uint32_t a = (stb) + OFF_BH + (wn * 64 + in * 16 + rsel) * ROWB + colb; \
                LDSM4(bh[in], a);                                                   \
                LDSM4(bl[in], a + (OFF_BL - OFF_BH));                               \
            }                                                                       \
            _Pragma("unroll")                                                       \
            for (int im = 0; im < 4; im++) {                                        \
                _Pragma("unroll")                                                   \
                for (int jn = 0; jn < 8; jn++) {                                    \
                    const int g = jn >> 1, h = jn & 1;                              \
                    MMA16816(acc[im][jn], ah[im], bh[g][h], bh[g][h + 2]);          \
                    MMA16816(acc[im][jn], ah[im], bl[g][h], bl[g][h + 2]);          \
                    MMA16816(acc[im][jn], al[im], bh[g][h], bh[g][h + 2]);          \
                }                                                                   \
            }                                                                       \
        }                                                                           \
    } while (0)

// ============================================================================
// GEMM1: h = silu(gather(emb) @ W1 + b1) -> bf16 hi/lo.  96 chunks.
// ============================================================================
#define G1_NCHUNK (K1_N / 32)   // 96

__global__ __launch_bounds__(512, 1)
void kgram_gemm1_mma(const int* __restrict__ tokens,
                     const __nv_bfloat16* __restrict__ eh,
                     const __nv_bfloat16* __restrict__ el,
                     const __nv_bfloat16* __restrict__ w1h,
                     const __nv_bfloat16* __restrict__ w1l,
                     const float* __restrict__ b1)
{
    extern __shared__ char smem[];
    const uint32_t sb = smem_u32(smem);
    const int tid  = threadIdx.x;
    const int wid  = tid >> 5;
    const int lane = tid & 31;
    const int wm   = wid >> 2;          // 0..3
    const int wn   = wid & 3;           // 0..3

    const int rowBase = blockIdx.x * 256;
    const int colBase = blockIdx.y * 256;

    float acc[4][8][4];
    #pragma unroll
    for (int i = 0; i < 4; i++)
        #pragma unroll
        for (int j = 0; j < 8; j++)
            #pragma unroll
            for (int e = 0; e < 4; e++) acc[i][j][e] = 0.f;

    const int ldRow0 = tid >> 2;        // 0..127
    const int ldSeg  = tid & 3;
    const int ldCol  = ldSeg * 16;

    auto load_stage = [&](int c) {
        const int c0 = c * 32;
        const uint32_t stb = sb + (c & 1) * STAGE_B;
        const int kidx = c0 + ldSeg * 8;
        const int slot = kidx >> 10;
        const int off  = kidx & 1023;
        // A: gathered embedding rows (256 rows, hi+lo)
        #pragma unroll
        for (int it = 0; it < 2; it++) {
            const int row = ldRow0 + it * 128;
            const int r = rowBase + row;
            const int t = r >> 2;
            const int b = r & 3;
            const int tt = t - KCTX + slot;
            int tok = 0;
            if (tt >= 0) tok = tokens[tt * B_N + b];
            if (tok < 0) tok = 0;
            if (tok >= V_N) tok = V_N - 1;
            const size_t gA = (size_t)tok * E_N + off;
            const uint32_t d = stb + row * ROWB + ldCol;
            CP16(d + OFF_AH, eh + gA);
            CP16(d + OFF_AL, el + gA);
        }
        // B: W1^T (256 rows, hi+lo)
        #pragma unroll
        for (int it = 0; it < 2; it++) {
            const int row = ldRow0 + it * 128;
            const uint32_t d = stb + row * ROWB + ldCol;
            const size_t gB = (size_t)(colBase + row) * K1_N + c0 + ldSeg * 8;
            CP16(d + OFF_BH, w1h + gB);
            CP16(d + OFF_BL, w1l + gB);
        }
    };

    load_stage(0); CP_COMMIT();

    const int rsel  = lane & 15;
    const int cselB = (lane >> 4) * 16;

    for (int c = 0; c < G1_NCHUNK; c++) {
        CP_WAIT0();            // stage c resident (this thread's groups)
        __syncthreads();       // all threads' stage-c data visible; all done with buf (c+1)&1
        if (c + 1 < G1_NCHUNK) { load_stage(c + 1); CP_COMMIT(); }
        const uint32_t stb = sb + (c & 1) * STAGE_B;
        COMPUTE_CHUNK(stb);
    }

    // Epilogue: +b1, silu, split -> g_hh/g_hl
    const int mw = rowBase + wm * 64;
    const int nw = colBase + wn * 64;
    #pragma unroll
    for (int im = 0; im < 4; im++) {
        const int r0 = mw + im * 16 + (lane >> 2);
        #pragma unroll
        for (int jn = 0; jn < 8; jn++) {
            const int col = nw + jn * 8 + (lane & 3) * 2;
            const float2 bb = *reinterpret_cast<const float2*>(&b1[col]);
            float v00 = acc[im][jn][0] + bb.x;
            float v01 = acc[im][jn][1] + bb.y;
            float v10 = acc[im][jn][2] + bb.x;
            float v11 = acc[im][jn][3] + bb.y;
            v00 = v00 / (1.f + expf(-v00));
            v01 = v01 / (1.f + expf(-v01));
            v10 = v10 / (1.f + expf(-v10));
            v11 = v11 / (1.f + expf(-v11));
            __nv_bfloat16 h00, l00, h01, l01, h10, l10, h11, l11;
            split_bf16(v00, h00, l00); split_bf16(v01, h01, l01);
            split_bf16(v10, h10, l10); split_bf16(v11, h11, l11);
            *reinterpret_cast<__nv_bfloat162*>(g_hh + (size_t)r0 * H_N + col) =
                __nv_bfloat162(h00, h01);
            *reinterpret_cast<__nv_bfloat162*>(g_hl + (size_t)r0 * H_N + col) =
                __nv_bfloat162(l00, l01);
            *reinterpret_cast<__nv_bfloat162*>(g_hh + (size_t)(r0 + 8) * H_N + col) =
                __nv_bfloat162(h10, h11);
            *reinterpret_cast<__nv_bfloat162*>(g_hl + (size_t)(r0 + 8) * H_N + col) =
                __nv_bfloat162(l10, l11);
        }
    }
}

// ============================================================================
// GEMM2: logits = h @ Wout + bout.  64 chunks.
// ============================================================================
#define G2_NCHUNK (H_N / 32)    // 64

__global__ __launch_bounds__(512, 1)
void kgram_gemm2_mma(const __nv_bfloat16* __restrict__ hh,
                     const __nv_bfloat16* __restrict__ hl,
                     const __nv_bfloat16* __restrict__ wh,
                     const __nv_bfloat16* __restrict__ wl,
                     const float* __restrict__ bout,
                     float* __restrict__ out)
{
    extern __shared__ char smem[];
    const uint32_t sb = smem_u32(smem);
    const int tid  = threadIdx.x;
    const int wid  = tid >> 5;
    const int lane = tid & 31;
    const int wm   = wid >> 2;
    const int wn   = wid & 3;

    const int rowBase = blockIdx.x * 256;   // M fastest -> B-strip reuse in L2
    const int colBase = blockIdx.y * 256;

    float acc[4][8][4];
    #pragma unroll
    for (int i = 0; i < 4; i++)
        #pragma unroll
        for (int j = 0; j < 8; j++)
            #pragma unroll
            for (int e = 0; e < 4; e++) acc[i][j][e] = 0.f;

    const int ldRow0 = tid >> 2;
    const int ldCol  = (tid & 3) * 16;

    auto load_stage = [&](int c) {
        const int c0 = c * 32;
        const uint32_t stb = sb + (c & 1) * STAGE_B;
        #pragma unroll
        for (int it = 0; it < 2; it++) {
            const int row = ldRow0 + it * 128;
            const uint32_t d = stb + row * ROWB + ldCol;
            const size_t gA = (size_t)(rowBase + row) * H_N + c0 + (ldCol >> 1);
            CP16(d + OFF_AH, hh + gA);
            CP16(d + OFF_AL, hl + gA);
            const size_t gB = (size_t)(colBase + row) * H_N + c0 + (ldCol >> 1);
            CP16(d + OFF_BH, wh + gB);
            CP16(d + OFF_BL, wl + gB);
        }
    };

    load_stage(0); CP_COMMIT();

    const int rsel  = lane & 15;
    const int cselB = (lane >> 4) * 16;

    for (int c = 0; c < G2_NCHUNK; c++) {
        CP_WAIT0();
        __syncthreads();
        if (c + 1 < G2_NCHUNK) { load_stage(c + 1); CP_COMMIT(); }
        const uint32_t stb = sb + (c & 1) * STAGE_B;
        COMPUTE_CHUNK(stb);
    }

    // Epilogue: +bout -> gmem
    const int mw = rowBase + wm * 64;
    const int nw = colBase + wn * 64;
    #pragma unroll
    for (int im = 0; im < 4; im++) {
        const int r0 = mw + im * 16 + (lane >> 2);
        #pragma unroll
        for (int jn = 0; jn < 8; jn++) {
            const int col = nw + jn * 8 + (lane & 3) * 2;
            const float2 bb = *reinterpret_cast<const float2*>(&bout[col]);
            float2 o0, o1;
            o0.x = acc[im][jn][0] + bb.x;
            o0.y = acc[im][jn][1] + bb.y;
            o1.x = acc[im][jn][2] + bb.x;
            o1.y = acc[im][jn][3] + bb.y;
            *reinterpret_cast<float2*>(&out[(size_t)r0 * V_N + col])       = o0;
            *reinterpret_cast<float2*>(&out[(size_t)(r0 + 8) * V_N + col]) = o1;
        }
    }
}

// ---------------------------------------------------------------------------
// Launch
// ---------------------------------------------------------------------------
extern "C" void kernel_launch(void* const* d_in, const int* in_sizes, int n_in,
                              void* d_out, int out_size)
{
    const int*   tokens = (const int*)d_in[0];     // (T, B) int32
    const float* emb    = (const float*)d_in[1];   // (V, E)
    const float* W1     = (const float*)d_in[2];   // (K*E, H)
    const float* b1     = (const float*)d_in[3];   // (H,)
    const float* Wout   = (const float*)d_in[4];   // (H, V)
    const float* bout   = (const float*)d_in[5];   // (V,)
    float*       out    = (float*)d_out;           // (T, B, V) fp32

    __nv_bfloat16 *hh, *hl, *wh, *wl, *eh, *el, *w1h, *w1l;
    cudaGetSymbolAddress((void**)&hh, g_hh);
    cudaGetSymbolAddress((void**)&hl, g_hl);
    cudaGetSymbolAddress((void**)&wh, g_wh);
    cudaGetSymbolAddress((void**)&wl, g_wl);
    cudaGetSymbolAddress((void**)&eh, g_eh);
    cudaGetSymbolAddress((void**)&el, g_el);
    cudaGetSymbolAddress((void**)&w1h, g_w1h);
    cudaGetSymbolAddress((void**)&w1l, g_w1l);

    // Prepasses
    emb_split<<<(int)(((size_t)V_N * E_N) / 1024), 256>>>(emb);
    split_transpose<<<dim3(H_N / 32, K1_N / 32), 256>>>(W1, w1h, w1l, K1_N, H_N);
    split_transpose<<<dim3(V_N / 32, H_N / 32), 256>>>(Wout, wh, wl, H_N, V_N);

    // GEMM1 (HMMA bf16 3-split, gathered A) -> h bf16 hi/lo
    cudaFuncSetAttribute(kgram_gemm1_mma, cudaFuncAttributeMaxDynamicSharedMemorySize, GEMM_SMEM);
    kgram_gemm1_mma<<<dim3(M_N / 256, H_N / 256), 512, GEMM_SMEM>>>(tokens, eh, el, w1h, w1l, b1);

    // GEMM2 (HMMA bf16 3-split)
    cudaFuncSetAttribute(kgram_gemm2_mma, cudaFuncAttributeMaxDynamicSharedMemorySize, GEMM_SMEM);
    kgram_gemm2_mma<<<dim3(M_N / 256, V_N / 256), 512, GEMM_SMEM>>>(hh, hl, wh, wl, bout, out);
}

// round 8
// speedup vs baseline: 2.3318x; 2.3318x over previous
#include <cuda_runtime.h>
#include <cuda_fp16.h>
#include <cstdint>
#include <math.h>

// Problem constants (KGramMLPSeqModel: T=1024, B=4, V=32000, E=1024, K=3, H=2048)
#define T_N   1024
#define B_N   4
#define V_N   32000
#define E_N   1024
#define KCTX  3
#define H_N   2048
#define M_N   (T_N * B_N)      // 4096
#define K1_N  (KCTX * E_N)     // 3072

// ---------------------------------------------------------------------------
// Device scratch (__device__ globals per allocation-free rule)
// ---------------------------------------------------------------------------
__device__ __half g_hh[(size_t)M_N * H_N];    // h hi   (M,H) K-major
__device__ __half g_hl[(size_t)M_N * H_N];    // h lo
__device__ __half g_wo[(size_t)V_N * H_N];    // Wout^T fp16 (V,H) K-major (single)
__device__ __half g_eh[(size_t)V_N * E_N];    // embedding hi (V,E)
__device__ __half g_el[(size_t)V_N * E_N];    // embedding lo
__device__ __half g_w1[(size_t)H_N * K1_N];   // W1^T fp16 (H,K1) K-major (single)

// ---------------------------------------------------------------------------
// Helpers (baseline PTX only: plain compute_103 target)
// ---------------------------------------------------------------------------
__device__ __forceinline__ uint32_t smem_u32(const void* p) {
    uint32_t a;
    asm("{ .reg .u64 t; cvta.to.shared.u64 t, %1; cvt.u32.u64 %0, t; }" : "=r"(a) : "l"(p));
    return a;
}
#define CP16(dst, src) \
    asm volatile("cp.async.cg.shared.global [%0], [%1], 16;" :: "r"(dst), "l"(src) : "memory")
#define CP_COMMIT() asm volatile("cp.async.commit_group;" ::: "memory")
#define CP_WAIT1()  asm volatile("cp.async.wait_group 1;" ::: "memory")

#define LDSM4(r, addr) \
    asm volatile("ldmatrix.sync.aligned.m8n8.x4.shared.b16 {%0,%1,%2,%3}, [%4];" \
        : "=r"((r)[0]), "=r"((r)[1]), "=r"((r)[2]), "=r"((r)[3]) : "r"(addr))

#define MMA16816(d, a, b0, b1) \
    asm volatile("mma.sync.aligned.m16n8k16.row.col.f32.f16.f16.f32 " \
        "{%0,%1,%2,%3}, {%4,%5,%6,%7}, {%8,%9}, {%0,%1,%2,%3};" \
        : "+f"((d)[0]), "+f"((d)[1]), "+f"((d)[2]), "+f"((d)[3]) \
        : "r"((a)[0]), "r"((a)[1]), "r"((a)[2]), "r"((a)[3]), "r"(b0), "r"(b1))

__device__ __forceinline__ void split_f16(float v, __half& hi, __half& lo) {
    hi = __float2half_rn(v);
    lo = __float2half_rn(v - __half2float(hi));
}

// ---------------------------------------------------------------------------
// Prepass A: embedding fp32 -> fp16 hi/lo, same layout
// ---------------------------------------------------------------------------
__global__ __launch_bounds__(256)
void emb_split(const float* __restrict__ emb)
{
    const size_t i4 = ((size_t)blockIdx.x * 256 + threadIdx.x) * 4;
    const float4 v = *reinterpret_cast<const float4*>(emb + i4);
    __half h0, l0, h1, l1, h2, l2, h3, l3;
    split_f16(v.x, h0, l0); split_f16(v.y, h1, l1);
    split_f16(v.z, h2, l2); split_f16(v.w, h3, l3);
    __half2* oh = reinterpret_cast<__half2*>(g_eh + i4);
    __half2* ol = reinterpret_cast<__half2*>(g_el + i4);
    oh[0] = __half2(h0, h1); oh[1] = __half2(h2, h3);
    ol[0] = __half2(l0, l1); ol[1] = __half2(l2, l3);
}

// ---------------------------------------------------------------------------
// Prepass B: transpose to fp16 (single): in (R, C) fp32 -> out (C, R) fp16
// ---------------------------------------------------------------------------
__global__ __launch_bounds__(256)
void transpose_f16(const float* __restrict__ in,
                   __half* __restrict__ o,
                   int R, int C)
{
    __shared__ float tile[32][33];
    const int tx = threadIdx.x & 31;
    const int ty = threadIdx.x >> 5;          // 0..7
    const int cBase = blockIdx.x * 32;
    const int rBase = blockIdx.y * 32;

    #pragma unroll
    for (int j = 0; j < 4; j++)
        tile[ty + j * 8][tx] = in[(size_t)(rBase + ty + j * 8) * C + cBase + tx];
    __syncthreads();
    #pragma unroll
    for (int j = 0; j < 4; j++) {
        const int n = cBase + ty + j * 8;
        const int k = rBase + tx;
        o[(size_t)n * R + k] = __float2half_rn(tile[tx][ty + j * 8]);
    }
}

// ---------------------------------------------------------------------------
// Shared GEMM geometry (both GEMMs):
//   BM=128, BN=256, BK=32; 8 warps (2M x 4N), warp tile 64x64; 256 threads.
//   A split hi/lo fp16, B single fp16 -> 2 MMA products (product-major).
//   ROWB=80 (64B data + 16B pad) -> conflict-free ldmatrix phases.
//   3-stage cp.async pipeline, loads issued before compute.
// ---------------------------------------------------------------------------
#define ROWB      80
#define A_BYTES   (128 * ROWB)     // 10240
#define B_BYTES   (256 * ROWB)     // 20480
#define OFF_AH    0
#define OFF_AL    A_BYTES
#define OFF_B     (2 * A_BYTES)
#define STAGE_B   (2 * A_BYTES + B_BYTES)   // 40960
#define NSTAGE    3
#define GEMM_SMEM (NSTAGE * STAGE_B)        // 122880

// One 32-k chunk, warp tile 64x64 (acc[4][8][4]); 2 products, product-major.
#define COMPUTE_CHUNK(stb)                                                          \
    do {                                                                            \
        _Pragma("unroll")                                                           \
        for (int kk = 0; kk < 2; kk++) {                                            \
            const uint32_t colb = cselB + kk * 32;                                  \
            uint32_t ah[4][4], al[4][4];                                            \
            _Pragma("unroll")                                                       \
            for (int im = 0; im < 4; im++) {                                        \
                const uint32_t a = (stb) + OFF_AH + (wm * 64 + im * 16 + rsel) * ROWB + colb; \
                LDSM4(ah[im], a);                                                   \
                LDSM4(al[im], a + (OFF_AL - OFF_AH));                               \
            }                                                                       \
            uint32_t bf[4][4];                                                      \
            _Pragma("unroll")                                                       \
            for (int in = 0; in < 4; in++) {                                        \
                const uint32_t a = (stb) + OFF_B + (wn * 64 + in * 16 + rsel) * ROWB + colb; \
                LDSM4(bf[in], a);                                                   \
            }                                                                       \
            _Pragma("unroll")                                                       \
            for (int im = 0; im < 4; im++)                                          \
                _Pragma("unroll")                                                   \
                for (int jn = 0; jn < 8; jn++)                                      \
                    MMA16816(acc[im][jn], ah[im], bf[jn >> 1][jn & 1], bf[jn >> 1][(jn & 1) + 2]); \
            _Pragma("unroll")                                                       \
            for (int im = 0; im < 4; im++)                                          \
                _Pragma("unroll")                                                   \
                for (int jn = 0; jn < 8; jn++)                                      \
                    MMA16816(acc[im][jn], al[im], bf[jn >> 1][jn & 1], bf[jn >> 1][(jn & 1) + 2]); \
        }                                                                           \
    } while (0)

// ============================================================================
// GEMM1: h = silu(gather(emb) @ W1 + b1) -> fp16 hi/lo.  96 chunks.
// ============================================================================
#define G1_NCHUNK (K1_N / 32)   // 96

__global__ __launch_bounds__(256, 1)
void kgram_gemm1_mma(const int* __restrict__ tokens,
                     const __half* __restrict__ eh,
                     const __half* __restrict__ el,
                     const __half* __restrict__ w1,
                     const float* __restrict__ b1)
{
    extern __shared__ char smem[];
    const uint32_t sb = smem_u32(smem);
    const int tid  = threadIdx.x;
    const int wid  = tid >> 5;
    const int lane = tid & 31;
    const int wm   = wid >> 2;          // 0..1
    const int wn   = wid & 3;           // 0..3

    const int rowBase = blockIdx.x * 128;
    const int colBase = blockIdx.y * 256;

    float acc[4][8][4];
    #pragma unroll
    for (int i = 0; i < 4; i++)
        #pragma unroll
        for (int j = 0; j < 8; j++)
            #pragma unroll
            for (int e = 0; e < 4; e++) acc[i][j][e] = 0.f;

    const int ldRow0 = tid >> 2;        // 0..63
    const int ldSeg  = tid & 3;
    const int ldCol  = ldSeg * 16;

    auto load_stage = [&](int c) {
        const int c0 = c * 32;
        const uint32_t stb = sb + (c % NSTAGE) * STAGE_B;
        const int kidx = c0 + ldSeg * 8;
        const int slot = kidx >> 10;
        const int off  = kidx & 1023;
        // A: gathered embedding rows (128 rows, hi+lo)
        #pragma unroll
        for (int it = 0; it < 2; it++) {
            const int row = ldRow0 + it * 64;
            const int r = rowBase + row;
            const int t = r >> 2;
            const int b = r & 3;
            const int tt = t - KCTX + slot;
            int tok = 0;
            if (tt >= 0) tok = tokens[tt * B_N + b];
            if (tok < 0) tok = 0;
            if (tok >= V_N) tok = V_N - 1;
            const size_t gA = (size_t)tok * E_N + off;
            const uint32_t d = stb + row * ROWB + ldCol;
            CP16(d + OFF_AH, eh + gA);
            CP16(d + OFF_AL, el + gA);
        }
        // B: W1^T (256 rows, single fp16)
        #pragma unroll
        for (int it = 0; it < 4; it++) {
            const int row = ldRow0 + it * 64;
            const uint32_t d = stb + row * ROWB + ldCol;
            const size_t gB = (size_t)(colBase + row) * K1_N + c0 + ldSeg * 8;
            CP16(d + OFF_B, w1 + gB);
        }
    };

    load_stage(0); CP_COMMIT();
    load_stage(1); CP_COMMIT();

    const int rsel  = lane & 15;
    const int cselB = (lane >> 4) * 16;

    for (int c = 0; c < G1_NCHUNK; c++) {
        CP_WAIT1();
        __syncthreads();
        if (c + 2 < G1_NCHUNK) load_stage(c + 2);
        CP_COMMIT();
        const uint32_t stb = sb + (c % NSTAGE) * STAGE_B;
        COMPUTE_CHUNK(stb);
    }

    // Epilogue: +b1, silu, split -> g_hh/g_hl (fp16)
    const int mw = rowBase + wm * 64;
    const int nw = colBase + wn * 64;
    #pragma unroll
    for (int im = 0; im < 4; im++) {
        const int r0 = mw + im * 16 + (lane >> 2);
        #pragma unroll
        for (int jn = 0; jn < 8; jn++) {
            const int col = nw + jn * 8 + (lane & 3) * 2;
            const float2 bb = *reinterpret_cast<const float2*>(&b1[col]);
            float v00 = acc[im][jn][0] + bb.x;
            float v01 = acc[im][jn][1] + bb.y;
            float v10 = acc[im][jn][2] + bb.x;
            float v11 = acc[im][jn][3] + bb.y;
            v00 = v00 / (1.f + expf(-v00));
            v01 = v01 / (1.f + expf(-v01));
            v10 = v10 / (1.f + expf(-v10));
            v11 = v11 / (1.f + expf(-v11));
            __half h00, l00, h01, l01, h10, l10, h11, l11;
            split_f16(v00, h00, l00); split_f16(v01, h01, l01);
            split_f16(v10, h10, l10); split_f16(v11, h11, l11);
            *reinterpret_cast<__half2*>(g_hh + (size_t)r0 * H_N + col) = __half2(h00, h01);
            *reinterpret_cast<__half2*>(g_hl + (size_t)r0 * H_N + col) = __half2(l00, l01);
            *reinterpret_cast<__half2*>(g_hh + (size_t)(r0 + 8) * H_N + col) = __half2(h10, h11);
            *reinterpret_cast<__half2*>(g_hl + (size_t)(r0 + 8) * H_N + col) = __half2(l10, l11);
        }
    }
}

// ============================================================================
// GEMM2: logits = h @ Wout + bout.  64 chunks.
// ============================================================================
#define G2_NCHUNK (H_N / 32)    // 64

__global__ __launch_bounds__(256, 1)
void kgram_gemm2_mma(const __half* __restrict__ hh,
                     const __half* __restrict__ hl,
                     const __half* __restrict__ wo,
                     const float* __restrict__ bout,
                     float* __restrict__ out)
{
    extern __shared__ char smem[];
    const uint32_t sb = smem_u32(smem);
    const int tid  = threadIdx.x;
    const int wid  = tid >> 5;
    const int lane = tid & 31;
    const int wm   = wid >> 2;
    const int wn   = wid & 3;

    const int rowBase = blockIdx.x * 128;   // M fastest -> B-strip reuse in L2
    const int colBase = blockIdx.y * 256;

    float acc[4][8][4];
    #pragma unroll
    for (int i = 0; i < 4; i++)
        #pragma unroll
        for (int j = 0; j < 8; j++)
            #pragma unroll
            for (int e = 0; e < 4; e++) acc[i][j][e] = 0.f;

    const int ldRow0 = tid >> 2;
    const int ldCol  = (tid & 3) * 16;

    auto load_stage = [&](int c) {
        const int c0 = c * 32;
        const uint32_t stb = sb + (c % NSTAGE) * STAGE_B;
        #pragma unroll
        for (int it = 0; it < 2; it++) {
            const int row = ldRow0 + it * 64;
            const uint32_t d = stb + row * ROWB + ldCol;
            const size_t gA = (size_t)(rowBase + row) * H_N + c0 + (ldCol >> 1);
            CP16(d + OFF_AH, hh + gA);
            CP16(d + OFF_AL, hl + gA);
        }
        #pragma unroll
        for (int it = 0; it < 4; it++) {
            const int row = ldRow0 + it * 64;
            const uint32_t d = stb + row * ROWB + ldCol;
            const size_t gB = (size_t)(colBase + row) * H_N + c0 + (ldCol >> 1);
            CP16(d + OFF_B, wo + gB);
        }
    };

    load_stage(0); CP_COMMIT();
    load_stage(1); CP_COMMIT();

    const int rsel  = lane & 15;
    const int cselB = (lane >> 4) * 16;

    for (int c = 0; c < G2_NCHUNK; c++) {
        CP_WAIT1();
        __syncthreads();
        if (c + 2 < G2_NCHUNK) load_stage(c + 2);
        CP_COMMIT();
        const uint32_t stb = sb + (c % NSTAGE) * STAGE_B;
        COMPUTE_CHUNK(stb);
    }

    // Epilogue: +bout -> gmem
    const int mw = rowBase + wm * 64;
    const int nw = colBase + wn * 64;
    #pragma unroll
    for (int im = 0; im < 4; im++) {
        const int r0 = mw + im * 16 + (lane >> 2);
        #pragma unroll
        for (int jn = 0; jn < 8; jn++) {
            const int col = nw + jn * 8 + (lane & 3) * 2;
            const float2 bb = *reinterpret_cast<const float2*>(&bout[col]);
            float2 o0, o1;
            o0.x = acc[im][jn][0] + bb.x;
            o0.y = acc[im][jn][1] + bb.y;
            o1.x = acc[im][jn][2] + bb.x;
            o1.y = acc[im][jn][3] + bb.y;
            *reinterpret_cast<float2*>(&out[(size_t)r0 * V_N + col])       = o0;
            *reinterpret_cast<float2*>(&out[(size_t)(r0 + 8) * V_N + col]) = o1;
        }
    }
}

// ---------------------------------------------------------------------------
// Launch
// ---------------------------------------------------------------------------
extern "C" void kernel_launch(void* const* d_in, const int* in_sizes, int n_in,
                              void* d_out, int out_size)
{
    const int*   tokens = (const int*)d_in[0];     // (T, B) int32
    const float* emb    = (const float*)d_in[1];   // (V, E)
    const float* W1     = (const float*)d_in[2];   // (K*E, H)
    const float* b1     = (const float*)d_in[3];   // (H,)
    const float* Wout   = (const float*)d_in[4];   // (H, V)
    const float* bout   = (const float*)d_in[5];   // (V,)
    float*       out    = (float*)d_out;           // (T, B, V) fp32

    __half *hh, *hl, *wo, *eh, *el, *w1;
    cudaGetSymbolAddress((void**)&hh, g_hh);
    cudaGetSymbolAddress((void**)&hl, g_hl);
    cudaGetSymbolAddress((void**)&wo, g_wo);
    cudaGetSymbolAddress((void**)&eh, g_eh);
    cudaGetSymbolAddress((void**)&el, g_el);
    cudaGetSymbolAddress((void**)&w1, g_w1);

    // Prepasses
    emb_split<<<(int)(((size_t)V_N * E_N) / 1024), 256>>>(emb);
    transpose_f16<<<dim3(H_N / 32, K1_N / 32), 256>>>(W1, w1, K1_N, H_N);
    transpose_f16<<<dim3(V_N / 32, H_N / 32), 256>>>(Wout, wo, H_N, V_N);

    // GEMM1 (fp16 2-product, gathered A) -> h fp16 hi/lo
    cudaFuncSetAttribute(kgram_gemm1_mma, cudaFuncAttributeMaxDynamicSharedMemorySize, GEMM_SMEM);
    kgram_gemm1_mma<<<dim3(M_N / 128, H_N / 256), 256, GEMM_SMEM>>>(tokens, eh, el, w1, b1);

    // GEMM2 (fp16 2-product)
    cudaFuncSetAttribute(kgram_gemm2_mma, cudaFuncAttributeMaxDynamicSharedMemorySize, GEMM_SMEM);
    kgram_gemm2_mma<<<dim3(M_N / 128, V_N / 256), 256, GEMM_SMEM>>>(hh, hl, wo, bout, out);
}

// round 9
// speedup vs baseline: 2.3657x; 1.0145x over previous
#include <cuda_runtime.h>
#include <cuda_fp16.h>
#include <cstdint>
#include <math.h>

// Problem constants (KGramMLPSeqModel: T=1024, B=4, V=32000, E=1024, K=3, H=2048)
#define T_N   1024
#define B_N   4
#define V_N   32000
#define E_N   1024
#define KCTX  3
#define H_N   2048
#define M_N   (T_N * B_N)      // 4096
#define K1_N  (KCTX * E_N)     // 3072

// ---------------------------------------------------------------------------
// Device scratch (__device__ globals per allocation-free rule)
// ---------------------------------------------------------------------------
__device__ __half g_hh[(size_t)M_N * H_N];    // h hi   (M,H) K-major
__device__ __half g_hl[(size_t)M_N * H_N];    // h lo
__device__ __half g_wo[(size_t)V_N * H_N];    // Wout^T fp16 (V,H) K-major
__device__ __half g_eh[(size_t)V_N * E_N];    // embedding hi (V,E)
__device__ __half g_el[(size_t)V_N * E_N];    // embedding lo
__device__ __half g_w1[(size_t)H_N * K1_N];   // W1^T fp16 (H,K1) K-major

// ---------------------------------------------------------------------------
// Helpers (baseline PTX only: plain compute_103 target)
// ---------------------------------------------------------------------------
__device__ __forceinline__ uint32_t smem_u32(const void* p) {
    uint32_t a;
    asm("{ .reg .u64 t; cvta.to.shared.u64 t, %1; cvt.u32.u64 %0, t; }" : "=r"(a) : "l"(p));
    return a;
}
#define CP16(dst, src) \
    asm volatile("cp.async.cg.shared.global [%0], [%1], 16;" :: "r"(dst), "l"(src) : "memory")
#define CP_COMMIT() asm volatile("cp.async.commit_group;" ::: "memory")
#define CP_WAIT1()  asm volatile("cp.async.wait_group 1;" ::: "memory")

#define LDSM4(r, addr) \
    asm volatile("ldmatrix.sync.aligned.m8n8.x4.shared.b16 {%0,%1,%2,%3}, [%4];" \
        : "=r"((r)[0]), "=r"((r)[1]), "=r"((r)[2]), "=r"((r)[3]) : "r"(addr))

#define MMA16816(d, a, b0, b1) \
    asm volatile("mma.sync.aligned.m16n8k16.row.col.f32.f16.f16.f32 " \
        "{%0,%1,%2,%3}, {%4,%5,%6,%7}, {%8,%9}, {%0,%1,%2,%3};" \
        : "+f"((d)[0]), "+f"((d)[1]), "+f"((d)[2]), "+f"((d)[3]) \
        : "r"((a)[0]), "r"((a)[1]), "r"((a)[2]), "r"((a)[3]), "r"(b0), "r"(b1))

__device__ __forceinline__ void split_f16(float v, __half& hi, __half& lo) {
    hi = __float2half_rn(v);
    lo = __float2half_rn(v - __half2float(hi));
}

// ---------------------------------------------------------------------------
// Prepass A: embedding fp32 -> fp16 hi/lo, same layout
// ---------------------------------------------------------------------------
__global__ __launch_bounds__(256)
void emb_split(const float* __restrict__ emb)
{
    const size_t i4 = ((size_t)blockIdx.x * 256 + threadIdx.x) * 4;
    const float4 v = *reinterpret_cast<const float4*>(emb + i4);
    __half h0, l0, h1, l1, h2, l2, h3, l3;
    split_f16(v.x, h0, l0); split_f16(v.y, h1, l1);
    split_f16(v.z, h2, l2); split_f16(v.w, h3, l3);
    __half2* oh = reinterpret_cast<__half2*>(g_eh + i4);
    __half2* ol = reinterpret_cast<__half2*>(g_el + i4);
    oh[0] = __half2(h0, h1); oh[1] = __half2(h2, h3);
    ol[0] = __half2(l0, l1); ol[1] = __half2(l2, l3);
}

// ---------------------------------------------------------------------------
// Prepass B: transpose to fp16: in (R, C) fp32 -> out (C, R) fp16
// ---------------------------------------------------------------------------
__global__ __launch_bounds__(256)
void transpose_f16(const float* __restrict__ in,
                   __half* __restrict__ o,
                   int R, int C)
{
    __shared__ float tile[32][33];
    const int tx = threadIdx.x & 31;
    const int ty = threadIdx.x >> 5;          // 0..7
    const int cBase = blockIdx.x * 32;
    const int rBase = blockIdx.y * 32;

    #pragma unroll
    for (int j = 0; j < 4; j++)
        tile[ty + j * 8][tx] = in[(size_t)(rBase + ty + j * 8) * C + cBase + tx];
    __syncthreads();
    #pragma unroll
    for (int j = 0; j < 4; j++) {
        const int n = cBase + ty + j * 8;
        const int k = rBase + tx;
        o[(size_t)n * R + k] = __float2half_rn(tile[tx][ty + j * 8]);
    }
}

// ---------------------------------------------------------------------------
// Shared GEMM geometry (both GEMMs):
//   BM=128, BN=256, BK=32; 8 warps (2M x 4N), warp tile 64x64; 256 threads.
//   A split hi/lo fp16, B single fp16 -> 2 MMA products.
//   ROWB=80 (64B data + 16B pad) -> conflict-free ldmatrix phases.
//   3-stage cp.async pipeline; per chunk: ALL 24 LDSM up front, then
//   128 MMAs as one product-major burst (single latency exposure).
// ---------------------------------------------------------------------------
#define ROWB      80
#define A_BYTES   (128 * ROWB)     // 10240
#define B_BYTES   (256 * ROWB)     // 20480
#define OFF_AH    0
#define OFF_AL    A_BYTES
#define OFF_B     (2 * A_BYTES)
#define STAGE_B   (2 * A_BYTES + B_BYTES)   // 40960
#define NSTAGE    3
#define GEMM_SMEM (NSTAGE * STAGE_B)        // 122880

#define COMPUTE_CHUNK(stb)                                                          \
    do {                                                                            \
        uint32_t ah[2][4][4], al[2][4][4], bf[2][4][4];                             \
        _Pragma("unroll")                                                           \
        for (int kk = 0; kk < 2; kk++) {                                            \
            const uint32_t colb = cselB + kk * 32;                                  \
            _Pragma("unroll")                                                       \
            for (int im = 0; im < 4; im++) {                                        \
                const uint32_t a = (stb) + OFF_AH + (wm * 64 + im * 16 + rsel) * ROWB + colb; \
                LDSM4(ah[kk][im], a);                                               \
                LDSM4(al[kk][im], a + (OFF_AL - OFF_AH));                           \
            }                                                                       \
            _Pragma("unroll")                                                       \
            for (int in = 0; in < 4; in++) {                                        \
                const uint32_t a = (stb) + OFF_B + (wn * 64 + in * 16 + rsel) * ROWB + colb; \
                LDSM4(bf[kk][in], a);                                               \
            }                                                                       \
        }                                                                           \
        _Pragma("unroll")                                                           \
        for (int kk = 0; kk < 2; kk++)                                              \
            _Pragma("unroll")                                                       \
            for (int im = 0; im < 4; im++)                                          \
                _Pragma("unroll")                                                   \
                for (int jn = 0; jn < 8; jn++)                                      \
                    MMA16816(acc[im][jn], ah[kk][im],                               \
                             bf[kk][jn >> 1][jn & 1], bf[kk][jn >> 1][(jn & 1) + 2]); \
        _Pragma("unroll")                                                           \
        for (int kk = 0; kk < 2; kk++)                                              \
            _Pragma("unroll")                                                       \
            for (int im = 0; im < 4; im++)                                          \
                _Pragma("unroll")                                                   \
                for (int jn = 0; jn < 8; jn++)                                      \
                    MMA16816(acc[im][jn], al[kk][im],                               \
                             bf[kk][jn >> 1][jn & 1], bf[kk][jn >> 1][(jn & 1) + 2]); \
    } while (0)

// ============================================================================
// GEMM1: h = silu(gather(emb) @ W1 + b1) -> fp16 hi/lo.  96 chunks.
// ============================================================================
#define G1_NCHUNK (K1_N / 32)   // 96

__global__ __launch_bounds__(256, 1)
void kgram_gemm1_mma(const int* __restrict__ tokens,
                     const __half* __restrict__ eh,
                     const __half* __restrict__ el,
                     const __half* __restrict__ w1,
                     const float* __restrict__ b1)
{
    extern __shared__ char smem[];
    const uint32_t sb = smem_u32(smem);
    const int tid  = threadIdx.x;
    const int wid  = tid >> 5;
    const int lane = tid & 31;
    const int wm   = wid >> 2;          // 0..1
    const int wn   = wid & 3;           // 0..3

    const int rowBase = blockIdx.x * 128;
    const int colBase = blockIdx.y * 256;

    float acc[4][8][4];
    #pragma unroll
    for (int i = 0; i < 4; i++)
        #pragma unroll
        for (int j = 0; j < 8; j++)
            #pragma unroll
            for (int e = 0; e < 4; e++) acc[i][j][e] = 0.f;

    const int ldRow0 = tid >> 2;        // 0..63
    const int ldSeg  = tid & 3;
    const int ldCol  = ldSeg * 16;

    auto load_stage = [&](int c) {
        const int c0 = c * 32;
        const uint32_t stb = sb + (c % NSTAGE) * STAGE_B;
        const int kidx = c0 + ldSeg * 8;
        const int slot = kidx >> 10;
        const int off  = kidx & 1023;
        // A: gathered embedding rows (128 rows, hi+lo)
        #pragma unroll
        for (int it = 0; it < 2; it++) {
            const int row = ldRow0 + it * 64;
            const int r = rowBase + row;
            const int t = r >> 2;
            const int b = r & 3;
            const int tt = t - KCTX + slot;
            int tok = 0;
            if (tt >= 0) tok = tokens[tt * B_N + b];
            if (tok < 0) tok = 0;
            if (tok >= V_N) tok = V_N - 1;
            const size_t gA = (size_t)tok * E_N + off;
            const uint32_t d = stb + row * ROWB + ldCol;
            CP16(d + OFF_AH, eh + gA);
            CP16(d + OFF_AL, el + gA);
        }
        // B: W1^T (256 rows, single fp16)
        #pragma unroll
        for (int it = 0; it < 4; it++) {
            const int row = ldRow0 + it * 64;
            const uint32_t d = stb + row * ROWB + ldCol;
            const size_t gB = (size_t)(colBase + row) * K1_N + c0 + ldSeg * 8;
            CP16(d + OFF_B, w1 + gB);
        }
    };

    load_stage(0); CP_COMMIT();
    load_stage(1); CP_COMMIT();

    const int rsel  = lane & 15;
    const int cselB = (lane >> 4) * 16;

    for (int c = 0; c < G1_NCHUNK; c++) {
        CP_WAIT1();
        __syncthreads();
        if (c + 2 < G1_NCHUNK) load_stage(c + 2);
        CP_COMMIT();
        const uint32_t stb = sb + (c % NSTAGE) * STAGE_B;
        COMPUTE_CHUNK(stb);
    }

    // Epilogue: +b1, silu, split -> g_hh/g_hl (fp16)
    const int mw = rowBase + wm * 64;
    const int nw = colBase + wn * 64;
    #pragma unroll
    for (int im = 0; im < 4; im++) {
        const int r0 = mw + im * 16 + (lane >> 2);
        #pragma unroll
        for (int jn = 0; jn < 8; jn++) {
            const int col = nw + jn * 8 + (lane & 3) * 2;
            const float2 bb = *reinterpret_cast<const float2*>(&b1[col]);
            float v00 = acc[im][jn][0] + bb.x;
            float v01 = acc[im][jn][1] + bb.y;
            float v10 = acc[im][jn][2] + bb.x;
            float v11 = acc[im][jn][3] + bb.y;
            v00 = v00 / (1.f + expf(-v00));
            v01 = v01 / (1.f + expf(-v01));
            v10 = v10 / (1.f + expf(-v10));
            v11 = v11 / (1.f + expf(-v11));
            __half h00, l00, h01, l01, h10, l10, h11, l11;
            split_f16(v00, h00, l00); split_f16(v01, h01, l01);
            split_f16(v10, h10, l10); split_f16(v11, h11, l11);
            *reinterpret_cast<__half2*>(g_hh + (size_t)r0 * H_N + col) = __half2(h00, h01);
            *reinterpret_cast<__half2*>(g_hl + (size_t)r0 * H_N + col) = __half2(l00, l01);
            *reinterpret_cast<__half2*>(g_hh + (size_t)(r0 + 8) * H_N + col) = __half2(h10, h11);
            *reinterpret_cast<__half2*>(g_hl + (size_t)(r0 + 8) * H_N + col) = __half2(l10, l11);
        }
    }
}

// ============================================================================
// GEMM2: logits = h @ Wout + bout.  64 chunks.
// ============================================================================
#define G2_NCHUNK (H_N / 32)    // 64

__global__ __launch_bounds__(256, 1)
void kgram_gemm2_mma(const __half* __restrict__ hh,
                     const __half* __restrict__ hl,
                     const __half* __restrict__ wo,
                     const float* __restrict__ bout,
                     float* __restrict__ out)
{
    extern __shared__ char smem[];
    const uint32_t sb = smem_u32(smem);
    const int tid  = threadIdx.x;
    const int wid  = tid >> 5;
    const int lane = tid & 31;
    const int wm   = wid >> 2;
    const int wn   = wid & 3;

    const int rowBase = blockIdx.x * 128;   // M fastest -> B-strip reuse in L2
    const int colBase = blockIdx.y * 256;

    float acc[4][8][4];
    #pragma unroll
    for (int i = 0; i < 4; i++)
        #pragma unroll
        for (int j = 0; j < 8; j++)
            #pragma unroll
            for (int e = 0; e < 4; e++) acc[i][j][e] = 0.f;

    const int ldRow0 = tid >> 2;
    const int ldCol  = (tid & 3) * 16;
    const int kOff0  = ldCol >> 1;

    // Precomputed per-thread global base offsets (advance by +c*32 per chunk)
    const size_t baseA0 = (size_t)(rowBase + ldRow0)       * H_N + kOff0;
    const size_t baseA1 = (size_t)(rowBase + ldRow0 + 64)  * H_N + kOff0;
    const size_t baseB0 = (size_t)(colBase + ldRow0)       * H_N + kOff0;
    const size_t baseB1 = (size_t)(colBase + ldRow0 + 64)  * H_N + kOff0;
    const size_t baseB2 = (size_t)(colBase + ldRow0 + 128) * H_N + kOff0;
    const size_t baseB3 = (size_t)(colBase + ldRow0 + 192) * H_N + kOff0;
    const uint32_t dA0 = ldRow0 * ROWB + ldCol;
    const uint32_t dA1 = (ldRow0 + 64) * ROWB + ldCol;

    auto load_stage = [&](int c) {
        const int c0 = c * 32;
        const uint32_t stb = sb + (c % NSTAGE) * STAGE_B;
        CP16(stb + dA0 + OFF_AH, hh + baseA0 + c0);
        CP16(stb + dA0 + OFF_AL, hl + baseA0 + c0);
        CP16(stb + dA1 + OFF_AH, hh + baseA1 + c0);
        CP16(stb + dA1 + OFF_AL, hl + baseA1 + c0);
        CP16(stb + dA0 + OFF_B,                wo + baseB0 + c0);
        CP16(stb + dA1 + OFF_B,                wo + baseB1 + c0);
        CP16(stb + dA0 + 128 * ROWB + OFF_B,   wo + baseB2 + c0);
        CP16(stb + dA1 + 128 * ROWB + OFF_B,   wo + baseB3 + c0);
    };

    load_stage(0); CP_COMMIT();
    load_stage(1); CP_COMMIT();

    const int rsel  = lane & 15;
    const int cselB = (lane >> 4) * 16;

    for (int c = 0; c < G2_NCHUNK; c++) {
        CP_WAIT1();
        __syncthreads();
        if (c + 2 < G2_NCHUNK) load_stage(c + 2);
        CP_COMMIT();
        const uint32_t stb = sb + (c % NSTAGE) * STAGE_B;
        COMPUTE_CHUNK(stb);
    }

    // Epilogue: +bout -> gmem
    const int mw = rowBase + wm * 64;
    const int nw = colBase + wn * 64;
    #pragma unroll
    for (int im = 0; im < 4; im++) {
        const int r0 = mw + im * 16 + (lane >> 2);
        #pragma unroll
        for (int jn = 0; jn < 8; jn++) {
            const int col = nw + jn * 8 + (lane & 3) * 2;
            const float2 bb = *reinterpret_cast<const float2*>(&bout[col]);
            float2 o0, o1;
            o0.x = acc[im][jn][0] + bb.x;
            o0.y = acc[im][jn][1] + bb.y;
            o1.x = acc[im][jn][2] + bb.x;
            o1.y = acc[im][jn][3] + bb.y;
            *reinterpret_cast<float2*>(&out[(size_t)r0 * V_N + col])       = o0;
            *reinterpret_cast<float2*>(&out[(size_t)(r0 + 8) * V_N + col]) = o1;
        }
    }
}

// ---------------------------------------------------------------------------
// Launch
// ---------------------------------------------------------------------------
extern "C" void kernel_launch(void* const* d_in, const int* in_sizes, int n_in,
                              void* d_out, int out_size)
{
    const int*   tokens = (const int*)d_in[0];     // (T, B) int32
    const float* emb    = (const float*)d_in[1];   // (V, E)
    const float* W1     = (const float*)d_in[2];   // (K*E, H)
    const float* b1     = (const float*)d_in[3];   // (H,)
    const float* Wout   = (const float*)d_in[4];   // (H, V)
    const float* bout   = (const float*)d_in[5];   // (V,)
    float*       out    = (float*)d_out;           // (T, B, V) fp32

    __half *hh, *hl, *wo, *eh, *el, *w1;
    cudaGetSymbolAddress((void**)&hh, g_hh);
    cudaGetSymbolAddress((void**)&hl, g_hl);
    cudaGetSymbolAddress((void**)&wo, g_wo);
    cudaGetSymbolAddress((void**)&eh, g_eh);
    cudaGetSymbolAddress((void**)&el, g_el);
    cudaGetSymbolAddress((void**)&w1, g_w1);

    // Prepasses
    emb_split<<<(int)(((size_t)V_N * E_N) / 1024), 256>>>(emb);
    transpose_f16<<<dim3(H_N / 32, K1_N / 32), 256>>>(W1, w1, K1_N, H_N);
    transpose_f16<<<dim3(V_N / 32, H_N / 32), 256>>>(Wout, wo, H_N, V_N);

    // GEMM1 (fp16 2-product, gathered A) -> h fp16 hi/lo
    cudaFuncSetAttribute(kgram_gemm1_mma, cudaFuncAttributeMaxDynamicSharedMemorySize, GEMM_SMEM);
    kgram_gemm1_mma<<<dim3(M_N / 128, H_N / 256), 256, GEMM_SMEM>>>(tokens, eh, el, w1, b1);

    // GEMM2 (fp16 2-product)
    cudaFuncSetAttribute(kgram_gemm2_mma, cudaFuncAttributeMaxDynamicSharedMemorySize, GEMM_SMEM);
    kgram_gemm2_mma<<<dim3(M_N / 128, V_N / 256), 256, GEMM_SMEM>>>(hh, hl, wo, bout, out);
}

// round 10
// speedup vs baseline: 2.3743x; 1.0036x over previous
#include <cuda_runtime.h>
#include <cuda_fp16.h>
#include <cstdint>
#include <math.h>

// Problem constants (KGramMLPSeqModel: T=1024, B=4, V=32000, E=1024, K=3, H=2048)
#define T_N   1024
#define B_N   4
#define V_N   32000
#define E_N   1024
#define KCTX  3
#define H_N   2048
#define M_N   (T_N * B_N)      // 4096
#define K1_N  (KCTX * E_N)     // 3072

// ---------------------------------------------------------------------------
// Device scratch (__device__ globals per allocation-free rule)
// ---------------------------------------------------------------------------
__device__ __half g_hh[(size_t)M_N * H_N];    // h hi   (M,H) K-major
__device__ __half g_hl[(size_t)M_N * H_N];    // h lo
__device__ __half g_wo[(size_t)V_N * H_N];    // Wout^T fp16 (V,H) K-major
__device__ __half g_eh[(size_t)V_N * E_N];    // embedding hi (V,E)
__device__ __half g_el[(size_t)V_N * E_N];    // embedding lo
__device__ __half g_w1[(size_t)H_N * K1_N];   // W1^T fp16 (H,K1) K-major

// ---------------------------------------------------------------------------
// Helpers (baseline PTX only: plain compute_103 target)
// ---------------------------------------------------------------------------
__device__ __forceinline__ uint32_t smem_u32(const void* p) {
    uint32_t a;
    asm("{ .reg .u64 t; cvta.to.shared.u64 t, %1; cvt.u32.u64 %0, t; }" : "=r"(a) : "l"(p));
    return a;
}
#define CP16(dst, src) \
    asm volatile("cp.async.cg.shared.global [%0], [%1], 16;" :: "r"(dst), "l"(src) : "memory")
#define CP_COMMIT() asm volatile("cp.async.commit_group;" ::: "memory")
#define CP_WAIT1()  asm volatile("cp.async.wait_group 1;" ::: "memory")

#define LDSM4(r, addr) \
    asm volatile("ldmatrix.sync.aligned.m8n8.x4.shared.b16 {%0,%1,%2,%3}, [%4];" \
        : "=r"((r)[0]), "=r"((r)[1]), "=r"((r)[2]), "=r"((r)[3]) : "r"(addr))

#define MMA16816(d, a, b0, b1) \
    asm volatile("mma.sync.aligned.m16n8k16.row.col.f32.f16.f16.f32 " \
        "{%0,%1,%2,%3}, {%4,%5,%6,%7}, {%8,%9}, {%0,%1,%2,%3};" \
        : "+f"((d)[0]), "+f"((d)[1]), "+f"((d)[2]), "+f"((d)[3]) \
        : "r"((a)[0]), "r"((a)[1]), "r"((a)[2]), "r"((a)[3]), "r"(b0), "r"(b1))

__device__ __forceinline__ void split_f16(float v, __half& hi, __half& lo) {
    hi = __float2half_rn(v);
    lo = __float2half_rn(v - __half2float(hi));
}

// ---------------------------------------------------------------------------
// Prepass A: embedding fp32 -> fp16 hi/lo, same layout
// ---------------------------------------------------------------------------
__global__ __launch_bounds__(256)
void emb_split(const float* __restrict__ emb)
{
    const size_t i4 = ((size_t)blockIdx.x * 256 + threadIdx.x) * 4;
    const float4 v = *reinterpret_cast<const float4*>(emb + i4);
    __half h0, l0, h1, l1, h2, l2, h3, l3;
    split_f16(v.x, h0, l0); split_f16(v.y, h1, l1);
    split_f16(v.z, h2, l2); split_f16(v.w, h3, l3);
    __half2* oh = reinterpret_cast<__half2*>(g_eh + i4);
    __half2* ol = reinterpret_cast<__half2*>(g_el + i4);
    oh[0] = __half2(h0, h1); oh[1] = __half2(h2, h3);
    ol[0] = __half2(l0, l1); ol[1] = __half2(l2, l3);
}

// ---------------------------------------------------------------------------
// Prepass B: transpose to fp16: in (R, C) fp32 -> out (C, R) fp16
// ---------------------------------------------------------------------------
__global__ __launch_bounds__(256)
void transpose_f16(const float* __restrict__ in,
                   __half* __restrict__ o,
                   int R, int C)
{
    __shared__ float tile[32][33];
    const int tx = threadIdx.x & 31;
    const int ty = threadIdx.x >> 5;          // 0..7
    const int cBase = blockIdx.x * 32;
    const int rBase = blockIdx.y * 32;

    #pragma unroll
    for (int j = 0; j < 4; j++)
        tile[ty + j * 8][tx] = in[(size_t)(rBase + ty + j * 8) * C + cBase + tx];
    __syncthreads();
    #pragma unroll
    for (int j = 0; j < 4; j++) {
        const int n = cBase + ty + j * 8;
        const int k = rBase + tx;
        o[(size_t)n * R + k] = __float2half_rn(tile[tx][ty + j * 8]);
    }
}

// ---------------------------------------------------------------------------
// Shared GEMM geometry (both GEMMs):
//   BM=128, BN=256, BK=32; 512 threads, 16 warps (2M x 8N), warp tile 64x32.
//   -> 4 warps/SMSP for latency hiding; 64x32 tile fits the 128-reg cap.
//   A split hi/lo fp16, B single fp16 -> 2 MMA products.
//   ROWB=80 (64B data + 16B pad) -> conflict-free ldmatrix phases.
//   3-stage cp.async pipeline, loads issued before compute.
// ---------------------------------------------------------------------------
#define ROWB      80
#define A_BYTES   (128 * ROWB)     // 10240
#define B_BYTES   (256 * ROWB)     // 20480
#define OFF_AH    0
#define OFF_AL    A_BYTES
#define OFF_B     (2 * A_BYTES)
#define STAGE_B   (2 * A_BYTES + B_BYTES)   // 40960
#define NSTAGE    3
#define GEMM_SMEM (NSTAGE * STAGE_B)        // 122880

// One 32-k chunk, warp tile 64x32 (acc[4][4][4]); 2 products, per-kk blocks.
#define COMPUTE_CHUNK(stb)                                                          \
    do {                                                                            \
        _Pragma("unroll")                                                           \
        for (int kk = 0; kk < 2; kk++) {                                            \
            const uint32_t colb = cselB + kk * 32;                                  \
            uint32_t ah[4][4], al[4][4];                                            \
            _Pragma("unroll")                                                       \
            for (int im = 0; im < 4; im++) {                                        \
                const uint32_t a = (stb) + OFF_AH + (wm * 64 + im * 16 + rsel) * ROWB + colb; \
                LDSM4(ah[im], a);                                                   \
                LDSM4(al[im], a + (OFF_AL - OFF_AH));                               \
            }                                                                       \
            uint32_t bf[2][4];                                                      \
            _Pragma("unroll")                                                       \
            for (int in = 0; in < 2; in++) {                                        \
                const uint32_t a = (stb) + OFF_B + (wn * 32 + in * 16 + rsel) * ROWB + colb; \
                LDSM4(bf[in], a);                                                   \
            }                                                                       \
            _Pragma("unroll")                                                       \
            for (int im = 0; im < 4; im++)                                          \
                _Pragma("unroll")                                                   \
                for (int jn = 0; jn < 4; jn++)                                      \
                    MMA16816(acc[im][jn], ah[im], bf[jn >> 1][jn & 1], bf[jn >> 1][(jn & 1) + 2]); \
            _Pragma("unroll")                                                       \
            for (int im = 0; im < 4; im++)                                          \
                _Pragma("unroll")                                                   \
                for (int jn = 0; jn < 4; jn++)                                      \
                    MMA16816(acc[im][jn], al[im], bf[jn >> 1][jn & 1], bf[jn >> 1][(jn & 1) + 2]); \
        }                                                                           \
    } while (0)

// ============================================================================
// GEMM1: h = silu(gather(emb) @ W1 + b1) -> fp16 hi/lo.  96 chunks.
// ============================================================================
#define G1_NCHUNK (K1_N / 32)   // 96

__global__ __launch_bounds__(512, 1)
void kgram_gemm1_mma(const int* __restrict__ tokens,
                     const __half* __restrict__ eh,
                     const __half* __restrict__ el,
                     const __half* __restrict__ w1,
                     const float* __restrict__ b1)
{
    extern __shared__ char smem[];
    const uint32_t sb = smem_u32(smem);
    const int tid  = threadIdx.x;
    const int wid  = tid >> 5;
    const int lane = tid & 31;
    const int wm   = wid >> 3;          // 0..1 (M)
    const int wn   = wid & 7;           // 0..7 (N), 32 cols each

    const int rowBase = blockIdx.x * 128;
    const int colBase = blockIdx.y * 256;

    float acc[4][4][4];
    #pragma unroll
    for (int i = 0; i < 4; i++)
        #pragma unroll
        for (int j = 0; j < 4; j++)
            #pragma unroll
            for (int e = 0; e < 4; e++) acc[i][j][e] = 0.f;

    const int ldRow0 = tid >> 2;        // 0..127
    const int ldSeg  = tid & 3;
    const int ldCol  = ldSeg * 16;

    auto load_stage = [&](int c) {
        const int c0 = c * 32;
        const uint32_t stb = sb + (c % NSTAGE) * STAGE_B;
        const int kidx = c0 + ldSeg * 8;
        const int slot = kidx >> 10;
        const int off  = kidx & 1023;
        // A: gathered embedding row (128 rows, hi+lo); 1 row per thread
        {
            const int r = rowBase + ldRow0;
            const int t = r >> 2;
            const int b = r & 3;
            const int tt = t - KCTX + slot;
            int tok = 0;
            if (tt >= 0) tok = tokens[tt * B_N + b];
            if (tok < 0) tok = 0;
            if (tok >= V_N) tok = V_N - 1;
            const size_t gA = (size_t)tok * E_N + off;
            const uint32_t d = stb + ldRow0 * ROWB + ldCol;
            CP16(d + OFF_AH, eh + gA);
            CP16(d + OFF_AL, el + gA);
        }
        // B: W1^T (256 rows, single fp16); 2 rows per thread
        #pragma unroll
        for (int it = 0; it < 2; it++) {
            const int row = ldRow0 + it * 128;
            const uint32_t d = stb + row * ROWB + ldCol;
            const size_t gB = (size_t)(colBase + row) * K1_N + c0 + ldSeg * 8;
            CP16(d + OFF_B, w1 + gB);
        }
    };

    load_stage(0); CP_COMMIT();
    load_stage(1); CP_COMMIT();

    const int rsel  = lane & 15;
    const int cselB = (lane >> 4) * 16;

    for (int c = 0; c < G1_NCHUNK; c++) {
        CP_WAIT1();
        __syncthreads();
        if (c + 2 < G1_NCHUNK) load_stage(c + 2);
        CP_COMMIT();
        const uint32_t stb = sb + (c % NSTAGE) * STAGE_B;
        COMPUTE_CHUNK(stb);
    }

    // Epilogue: +b1, silu, split -> g_hh/g_hl (fp16)
    const int mw = rowBase + wm * 64;
    const int nw = colBase + wn * 32;
    #pragma unroll
    for (int im = 0; im < 4; im++) {
        const int r0 = mw + im * 16 + (lane >> 2);
        #pragma unroll
        for (int jn = 0; jn < 4; jn++) {
            const int col = nw + jn * 8 + (lane & 3) * 2;
            const float2 bb = *reinterpret_cast<const float2*>(&b1[col]);
            float v00 = acc[im][jn][0] + bb.x;
            float v01 = acc[im][jn][1] + bb.y;
            float v10 = acc[im][jn][2] + bb.x;
            float v11 = acc[im][jn][3] + bb.y;
            v00 = v00 / (1.f + expf(-v00));
            v01 = v01 / (1.f + expf(-v01));
            v10 = v10 / (1.f + expf(-v10));
            v11 = v11 / (1.f + expf(-v11));
            __half h00, l00, h01, l01, h10, l10, h11, l11;
            split_f16(v00, h00, l00); split_f16(v01, h01, l01);
            split_f16(v10, h10, l10); split_f16(v11, h11, l11);
            *reinterpret_cast<__half2*>(g_hh + (size_t)r0 * H_N + col) = __half2(h00, h01);
            *reinterpret_cast<__half2*>(g_hl + (size_t)r0 * H_N + col) = __half2(l00, l01);
            *reinterpret_cast<__half2*>(g_hh + (size_t)(r0 + 8) * H_N + col) = __half2(h10, h11);
            *reinterpret_cast<__half2*>(g_hl + (size_t)(r0 + 8) * H_N + col) = __half2(l10, l11);
        }
    }
}

// ============================================================================
// GEMM2: logits = h @ Wout + bout.  64 chunks.
// ============================================================================
#define G2_NCHUNK (H_N / 32)    // 64

__global__ __launch_bounds__(512, 1)
void kgram_gemm2_mma(const __half* __restrict__ hh,
                     const __half* __restrict__ hl,
                     const __half* __restrict__ wo,
                     const float* __restrict__ bout,
                     float* __restrict__ out)
{
    extern __shared__ char smem[];
    const uint32_t sb = smem_u32(smem);
    const int tid  = threadIdx.x;
    const int wid  = tid >> 5;
    const int lane = tid & 31;
    const int wm   = wid >> 3;          // 0..1
    const int wn   = wid & 7;           // 0..7

    const int rowBase = blockIdx.x * 128;   // M fastest -> B-strip reuse in L2
    const int colBase = blockIdx.y * 256;

    float acc[4][4][4];
    #pragma unroll
    for (int i = 0; i < 4; i++)
        #pragma unroll
        for (int j = 0; j < 4; j++)
            #pragma unroll
            for (int e = 0; e < 4; e++) acc[i][j][e] = 0.f;

    const int ldRow0 = tid >> 2;        // 0..127
    const int ldCol  = (tid & 3) * 16;
    const int kOff0  = ldCol >> 1;

    // Precomputed per-thread global base offsets (advance by +c*32 per chunk)
    const size_t baseA  = (size_t)(rowBase + ldRow0)       * H_N + kOff0;
    const size_t baseB0 = (size_t)(colBase + ldRow0)       * H_N + kOff0;
    const size_t baseB1 = (size_t)(colBase + ldRow0 + 128) * H_N + kOff0;
    const uint32_t dR0 = ldRow0 * ROWB + ldCol;
    const uint32_t dR1 = (ldRow0 + 128) * ROWB + ldCol;

    auto load_stage = [&](int c) {
        const int c0 = c * 32;
        const uint32_t stb = sb + (c % NSTAGE) * STAGE_B;
        CP16(stb + dR0 + OFF_AH, hh + baseA + c0);
        CP16(stb + dR0 + OFF_AL, hl + baseA + c0);
        CP16(stb + dR0 + OFF_B,  wo + baseB0 + c0);
        CP16(stb + dR1 + OFF_B,  wo + baseB1 + c0);
    };

    load_stage(0); CP_COMMIT();
    load_stage(1); CP_COMMIT();

    const int rsel  = lane & 15;
    const int cselB = (lane >> 4) * 16;

    for (int c = 0; c < G2_NCHUNK; c++) {
        CP_WAIT1();
        __syncthreads();
        if (c + 2 < G2_NCHUNK) load_stage(c + 2);
        CP_COMMIT();
        const uint32_t stb = sb + (c % NSTAGE) * STAGE_B;
        COMPUTE_CHUNK(stb);
    }

    // Epilogue: +bout -> gmem
    const int mw = rowBase + wm * 64;
    const int nw = colBase + wn * 32;
    #pragma unroll
    for (int im = 0; im < 4; im++) {
        const int r0 = mw + im * 16 + (lane >> 2);
        #pragma unroll
        for (int jn = 0; jn < 4; jn++) {
            const int col = nw + jn * 8 + (lane & 3) * 2;
            const float2 bb = *reinterpret_cast<const float2*>(&bout[col]);
            float2 o0, o1;
            o0.x = acc[im][jn][0] + bb.x;
            o0.y = acc[im][jn][1] + bb.y;
            o1.x = acc[im][jn][2] + bb.x;
            o1.y = acc[im][jn][3] + bb.y;
            *reinterpret_cast<float2*>(&out[(size_t)r0 * V_N + col])       = o0;
            *reinterpret_cast<float2*>(&out[(size_t)(r0 + 8) * V_N + col]) = o1;
        }
    }
}

// ---------------------------------------------------------------------------
// Launch
// ---------------------------------------------------------------------------
extern "C" void kernel_launch(void* const* d_in, const int* in_sizes, int n_in,
                              void* d_out, int out_size)
{
    const int*   tokens = (const int*)d_in[0];     // (T, B) int32
    const float* emb    = (const float*)d_in[1];   // (V, E)
    const float* W1     = (const float*)d_in[2];   // (K*E, H)
    const float* b1     = (const float*)d_in[3];   // (H,)
    const float* Wout   = (const float*)d_in[4];   // (H, V)
    const float* bout   = (const float*)d_in[5];   // (V,)
    float*       out    = (float*)d_out;           // (T, B, V) fp32

    __half *hh, *hl, *wo, *eh, *el, *w1;
    cudaGetSymbolAddress((void**)&hh, g_hh);
    cudaGetSymbolAddress((void**)&hl, g_hl);
    cudaGetSymbolAddress((void**)&wo, g_wo);
    cudaGetSymbolAddress((void**)&eh, g_eh);
    cudaGetSymbolAddress((void**)&el, g_el);
    cudaGetSymbolAddress((void**)&w1, g_w1);

    // Prepasses
    emb_split<<<(int)(((size_t)V_N * E_N) / 1024), 256>>>(emb);
    transpose_f16<<<dim3(H_N / 32, K1_N / 32), 256>>>(W1, w1, K1_N, H_N);
    transpose_f16<<<dim3(V_N / 32, H_N / 32), 256>>>(Wout, wo, H_N, V_N);

    // GEMM1 (fp16 2-product, gathered A) -> h fp16 hi/lo
    cudaFuncSetAttribute(kgram_gemm1_mma, cudaFuncAttributeMaxDynamicSharedMemorySize, GEMM_SMEM);
    kgram_gemm1_mma<<<dim3(M_N / 128, H_N / 256), 512, GEMM_SMEM>>>(tokens, eh, el, w1, b1);

    // GEMM2 (fp16 2-product)
    cudaFuncSetAttribute(kgram_gemm2_mma, cudaFuncAttributeMaxDynamicSharedMemorySize, GEMM_SMEM);
    kgram_gemm2_mma<<<dim3(M_N / 128, V_N / 256), 512, GEMM_SMEM>>>(hh, hl, wo, bout, out);
}

// round 11
// speedup vs baseline: 3.9014x; 1.6432x over previous
#include <cuda_runtime.h>
#include <cuda_fp16.h>
#include <cstdint>
#include <math.h>

// Problem constants (KGramMLPSeqModel: T=1024, B=4, V=32000, E=1024, K=3, H=2048)
#define T_N   1024
#define B_N   4
#define V_N   32000
#define E_N   1024
#define KCTX  3
#define H_N   2048
#define M_N   (T_N * B_N)      // 4096
#define K1_N  (KCTX * E_N)     // 3072

// ---------------------------------------------------------------------------
// Device scratch (__device__ globals per allocation-free rule)
// ---------------------------------------------------------------------------
__device__ __half g_hh[(size_t)M_N * H_N];    // h fp16 (M,H) K-major (single)
__device__ __half g_wo[(size_t)V_N * H_N];    // Wout^T fp16 (V,H) K-major
__device__ __half g_eh[(size_t)V_N * E_N];    // embedding hi (V,E)
__device__ __half g_el[(size_t)V_N * E_N];    // embedding lo
__device__ __half g_w1[(size_t)H_N * K1_N];   // W1^T fp16 (H,K1) K-major

// ---------------------------------------------------------------------------
// Helpers (baseline PTX only: plain compute_103 target)
// ---------------------------------------------------------------------------
__device__ __forceinline__ uint32_t smem_u32(const void* p) {
    uint32_t a;
    asm("{ .reg .u64 t; cvta.to.shared.u64 t, %1; cvt.u32.u64 %0, t; }" : "=r"(a) : "l"(p));
    return a;
}
#define CP16(dst, src) \
    asm volatile("cp.async.cg.shared.global [%0], [%1], 16;" :: "r"(dst), "l"(src) : "memory")
#define CP_COMMIT() asm volatile("cp.async.commit_group;" ::: "memory")
#define CP_WAIT1()  asm volatile("cp.async.wait_group 1;" ::: "memory")

#define LDSM4(r, addr) \
    asm volatile("ldmatrix.sync.aligned.m8n8.x4.shared.b16 {%0,%1,%2,%3}, [%4];" \
        : "=r"((r)[0]), "=r"((r)[1]), "=r"((r)[2]), "=r"((r)[3]) : "r"(addr))

#define MMA16816(d, a, b0, b1) \
    asm volatile("mma.sync.aligned.m16n8k16.row.col.f32.f16.f16.f32 " \
        "{%0,%1,%2,%3}, {%4,%5,%6,%7}, {%8,%9}, {%0,%1,%2,%3};" \
        : "+f"((d)[0]), "+f"((d)[1]), "+f"((d)[2]), "+f"((d)[3]) \
        : "r"((a)[0]), "r"((a)[1]), "r"((a)[2]), "r"((a)[3]), "r"(b0), "r"(b1))

__device__ __forceinline__ void split_f16(float v, __half& hi, __half& lo) {
    hi = __float2half_rn(v);
    lo = __float2half_rn(v - __half2float(hi));
}

// ---------------------------------------------------------------------------
// Prepass A: embedding fp32 -> fp16 hi/lo, same layout
// ---------------------------------------------------------------------------
__global__ __launch_bounds__(256)
void emb_split(const float* __restrict__ emb)
{
    const size_t i4 = ((size_t)blockIdx.x * 256 + threadIdx.x) * 4;
    const float4 v = *reinterpret_cast<const float4*>(emb + i4);
    __half h0, l0, h1, l1, h2, l2, h3, l3;
    split_f16(v.x, h0, l0); split_f16(v.y, h1, l1);
    split_f16(v.z, h2, l2); split_f16(v.w, h3, l3);
    __half2* oh = reinterpret_cast<__half2*>(g_eh + i4);
    __half2* ol = reinterpret_cast<__half2*>(g_el + i4);
    oh[0] = __half2(h0, h1); oh[1] = __half2(h2, h3);
    ol[0] = __half2(l0, l1); ol[1] = __half2(l2, l3);
}

// ---------------------------------------------------------------------------
// Prepass B: transpose to fp16: in (R, C) fp32 -> out (C, R) fp16
// ---------------------------------------------------------------------------
__global__ __launch_bounds__(256)
void transpose_f16(const float* __restrict__ in,
                   __half* __restrict__ o,
                   int R, int C)
{
    __shared__ float tile[32][33];
    const int tx = threadIdx.x & 31;
    const int ty = threadIdx.x >> 5;          // 0..7
    const int cBase = blockIdx.x * 32;
    const int rBase = blockIdx.y * 32;

    #pragma unroll
    for (int j = 0; j < 4; j++)
        tile[ty + j * 8][tx] = in[(size_t)(rBase + ty + j * 8) * C + cBase + tx];
    __syncthreads();
    #pragma unroll
    for (int j = 0; j < 4; j++) {
        const int n = cBase + ty + j * 8;
        const int k = rBase + tx;
        o[(size_t)n * R + k] = __float2half_rn(tile[tx][ty + j * 8]);
    }
}

// ---------------------------------------------------------------------------
// Shared GEMM geometry: BM=128, BN=256, BK=32; 512 threads, 16 warps (2Mx8N),
// warp tile 64x32; ROWB=80 conflict-free ldmatrix; 3-stage cp.async.
// GEMM1: A = emb hi/lo (2-product). GEMM2: A = h single (1-product).
// ---------------------------------------------------------------------------
#define ROWB      80
#define A_BYTES   (128 * ROWB)     // 10240
#define B_BYTES   (256 * ROWB)     // 20480
#define NSTAGE    3

// GEMM1 stage layout: AH | AL | B
#define G1_OFF_AH 0
#define G1_OFF_AL A_BYTES
#define G1_OFF_B  (2 * A_BYTES)
#define G1_STAGE  (2 * A_BYTES + B_BYTES)   // 40960
#define G1_SMEM   (NSTAGE * G1_STAGE)       // 122880

// GEMM2 stage layout: A | B
#define G2_OFF_A  0
#define G2_OFF_B  A_BYTES
#define G2_STAGE  (A_BYTES + B_BYTES)       // 30720
#define G2_SMEM   (NSTAGE * G2_STAGE)       // 92160

// 2-product chunk (A hi/lo), warp tile 64x32 (acc[4][4][4])
#define COMPUTE_CHUNK_2P(stb)                                                       \
    do {                                                                            \
        _Pragma("unroll")                                                           \
        for (int kk = 0; kk < 2; kk++) {                                            \
            const uint32_t colb = cselB + kk * 32;                                  \
            uint32_t ah[4][4], al[4][4];                                            \
            _Pragma("unroll")                                                       \
            for (int im = 0; im < 4; im++) {                                        \
                const uint32_t a = (stb) + G1_OFF_AH + (wm * 64 + im * 16 + rsel) * ROWB + colb; \
                LDSM4(ah[im], a);                                                   \
                LDSM4(al[im], a + (G1_OFF_AL - G1_OFF_AH));                         \
            }                                                                       \
            uint32_t bf[2][4];                                                      \
            _Pragma("unroll")                                                       \
            for (int in = 0; in < 2; in++) {                                        \
                const uint32_t a = (stb) + G1_OFF_B + (wn * 32 + in * 16 + rsel) * ROWB + colb; \
                LDSM4(bf[in], a);                                                   \
            }                                                                       \
            _Pragma("unroll")                                                       \
            for (int im = 0; im < 4; im++)                                          \
                _Pragma("unroll")                                                   \
                for (int jn = 0; jn < 4; jn++)                                      \
                    MMA16816(acc[im][jn], ah[im], bf[jn >> 1][jn & 1], bf[jn >> 1][(jn & 1) + 2]); \
            _Pragma("unroll")                                                       \
            for (int im = 0; im < 4; im++)                                          \
                _Pragma("unroll")                                                   \
                for (int jn = 0; jn < 4; jn++)                                      \
                    MMA16816(acc[im][jn], al[im], bf[jn >> 1][jn & 1], bf[jn >> 1][(jn & 1) + 2]); \
        }                                                                           \
    } while (0)

// 1-product chunk (A single), warp tile 64x32
#define COMPUTE_CHUNK_1P(stb)                                                       \
    do {                                                                            \
        _Pragma("unroll")                                                           \
        for (int kk = 0; kk < 2; kk++) {                                            \
            const uint32_t colb = cselB + kk * 32;                                  \
            uint32_t ah[4][4];                                                      \
            _Pragma("unroll")                                                       \
            for (int im = 0; im < 4; im++) {                                        \
                const uint32_t a = (stb) + G2_OFF_A + (wm * 64 + im * 16 + rsel) * ROWB + colb; \
                LDSM4(ah[im], a);                                                   \
            }                                                                       \
            uint32_t bf[2][4];                                                      \
            _Pragma("unroll")                                                       \
            for (int in = 0; in < 2; in++) {                                        \
                const uint32_t a = (stb) + G2_OFF_B + (wn * 32 + in * 16 + rsel) * ROWB + colb; \
                LDSM4(bf[in], a);                                                   \
            }                                                                       \
            _Pragma("unroll")                                                       \
            for (int im = 0; im < 4; im++)                                          \
                _Pragma("unroll")                                                   \
                for (int jn = 0; jn < 4; jn++)                                      \
                    MMA16816(acc[im][jn], ah[im], bf[jn >> 1][jn & 1], bf[jn >> 1][(jn & 1) + 2]); \
        }                                                                           \
    } while (0)

// ============================================================================
// GEMM1: h = silu(gather(emb) @ W1 + b1) -> fp16 (single).  96 chunks.
// ============================================================================
#define G1_NCHUNK (K1_N / 32)   // 96

__global__ __launch_bounds__(512, 1)
void kgram_gemm1_mma(const int* __restrict__ tokens,
                     const __half* __restrict__ eh,
                     const __half* __restrict__ el,
                     const __half* __restrict__ w1,
                     const float* __restrict__ b1)
{
    extern __shared__ char smem[];
    const uint32_t sb = smem_u32(smem);
    const int tid  = threadIdx.x;
    const int wid  = tid >> 5;
    const int lane = tid & 31;
    const int wm   = wid >> 3;          // 0..1 (M)
    const int wn   = wid & 7;           // 0..7 (N), 32 cols each

    const int rowBase = blockIdx.x * 128;
    const int colBase = blockIdx.y * 256;

    float acc[4][4][4];
    #pragma unroll
    for (int i = 0; i < 4; i++)
        #pragma unroll
        for (int j = 0; j < 4; j++)
            #pragma unroll
            for (int e = 0; e < 4; e++) acc[i][j][e] = 0.f;

    const int ldRow0 = tid >> 2;        // 0..127
    const int ldSeg  = tid & 3;
    const int ldCol  = ldSeg * 16;

    auto load_stage = [&](int c) {
        const int c0 = c * 32;
        const uint32_t stb = sb + (c % NSTAGE) * G1_STAGE;
        const int kidx = c0 + ldSeg * 8;
        const int slot = kidx >> 10;
        const int off  = kidx & 1023;
        // A: gathered embedding row (128 rows, hi+lo); 1 row per thread
        {
            const int r = rowBase + ldRow0;
            const int t = r >> 2;
            const int b = r & 3;
            const int tt = t - KCTX + slot;
            int tok = 0;
            if (tt >= 0) tok = tokens[tt * B_N + b];
            if (tok < 0) tok = 0;
            if (tok >= V_N) tok = V_N - 1;
            const size_t gA = (size_t)tok * E_N + off;
            const uint32_t d = stb + ldRow0 * ROWB + ldCol;
            CP16(d + G1_OFF_AH, eh + gA);
            CP16(d + G1_OFF_AL, el + gA);
        }
        // B: W1^T (256 rows, single fp16); 2 rows per thread
        #pragma unroll
        for (int it = 0; it < 2; it++) {
            const int row = ldRow0 + it * 128;
            const uint32_t d = stb + row * ROWB + ldCol;
            const size_t gB = (size_t)(colBase + row) * K1_N + c0 + ldSeg * 8;
            CP16(d + G1_OFF_B, w1 + gB);
        }
    };

    load_stage(0); CP_COMMIT();
    load_stage(1); CP_COMMIT();

    const int rsel  = lane & 15;
    const int cselB = (lane >> 4) * 16;

    for (int c = 0; c < G1_NCHUNK; c++) {
        CP_WAIT1();
        __syncthreads();
        if (c + 2 < G1_NCHUNK) load_stage(c + 2);
        CP_COMMIT();
        const uint32_t stb = sb + (c % NSTAGE) * G1_STAGE;
        COMPUTE_CHUNK_2P(stb);
    }

    // Epilogue: +b1, silu -> g_hh (fp16 single)
    const int mw = rowBase + wm * 64;
    const int nw = colBase + wn * 32;
    #pragma unroll
    for (int im = 0; im < 4; im++) {
        const int r0 = mw + im * 16 + (lane >> 2);
        #pragma unroll
        for (int jn = 0; jn < 4; jn++) {
            const int col = nw + jn * 8 + (lane & 3) * 2;
            const float2 bb = *reinterpret_cast<const float2*>(&b1[col]);
            float v00 = acc[im][jn][0] + bb.x;
            float v01 = acc[im][jn][1] + bb.y;
            float v10 = acc[im][jn][2] + bb.x;
            float v11 = acc[im][jn][3] + bb.y;
            v00 = v00 / (1.f + expf(-v00));
            v01 = v01 / (1.f + expf(-v01));
            v10 = v10 / (1.f + expf(-v10));
            v11 = v11 / (1.f + expf(-v11));
            *reinterpret_cast<__half2*>(g_hh + (size_t)r0 * H_N + col) =
                __half2(__float2half_rn(v00), __float2half_rn(v01));
            *reinterpret_cast<__half2*>(g_hh + (size_t)(r0 + 8) * H_N + col) =
                __half2(__float2half_rn(v10), __float2half_rn(v11));
        }
    }
}

// ============================================================================
// GEMM2: logits = h @ Wout + bout.  64 chunks, single product.
// ============================================================================
#define G2_NCHUNK (H_N / 32)    // 64

__global__ __launch_bounds__(512, 1)
void kgram_gemm2_mma(const __half* __restrict__ hh,
                     const __half* __restrict__ wo,
                     const float* __restrict__ bout,
                     float* __restrict__ out)
{
    extern __shared__ char smem[];
    const uint32_t sb = smem_u32(smem);
    const int tid  = threadIdx.x;
    const int wid  = tid >> 5;
    const int lane = tid & 31;
    const int wm   = wid >> 3;          // 0..1
    const int wn   = wid & 7;           // 0..7

    const int rowBase = blockIdx.x * 128;   // M fastest -> B-strip reuse in L2
    const int colBase = blockIdx.y * 256;

    float acc[4][4][4];
    #pragma unroll
    for (int i = 0; i < 4; i++)
        #pragma unroll
        for (int j = 0; j < 4; j++)
            #pragma unroll
            for (int e = 0; e < 4; e++) acc[i][j][e] = 0.f;

    const int ldRow0 = tid >> 2;        // 0..127
    const int ldCol  = (tid & 3) * 16;
    const int kOff0  = ldCol >> 1;

    // Precomputed per-thread global base offsets (advance by +c*32 per chunk)
    const size_t baseA  = (size_t)(rowBase + ldRow0)       * H_N + kOff0;
    const size_t baseB0 = (size_t)(colBase + ldRow0)       * H_N + kOff0;
    const size_t baseB1 = (size_t)(colBase + ldRow0 + 128) * H_N + kOff0;
    const uint32_t dR0 = ldRow0 * ROWB + ldCol;
    const uint32_t dR1 = (ldRow0 + 128) * ROWB + ldCol;

    auto load_stage = [&](int c) {
        const int c0 = c * 32;
        const uint32_t stb = sb + (c % NSTAGE) * G2_STAGE;
        CP16(stb + dR0 + G2_OFF_A, hh + baseA + c0);
        CP16(stb + dR0 + G2_OFF_B, wo + baseB0 + c0);
        CP16(stb + dR1 + G2_OFF_B, wo + baseB1 + c0);
    };

    load_stage(0); CP_COMMIT();
    load_stage(1); CP_COMMIT();

    const int rsel  = lane & 15;
    const int cselB = (lane >> 4) * 16;

    for (int c = 0; c < G2_NCHUNK; c++) {
        CP_WAIT1();
        __syncthreads();
        if (c + 2 < G2_NCHUNK) load_stage(c + 2);
        CP_COMMIT();
        const uint32_t stb = sb + (c % NSTAGE) * G2_STAGE;
        COMPUTE_CHUNK_1P(stb);
    }

    // Epilogue: +bout -> gmem
    const int mw = rowBase + wm * 64;
    const int nw = colBase + wn * 32;
    #pragma unroll
    for (int im = 0; im < 4; im++) {
        const int r0 = mw + im * 16 + (lane >> 2);
        #pragma unroll
        for (int jn = 0; jn < 4; jn++) {
            const int col = nw + jn * 8 + (lane & 3) * 2;
            const float2 bb = *reinterpret_cast<const float2*>(&bout[col]);
            float2 o0, o1;
            o0.x = acc[im][jn][0] + bb.x;
            o0.y = acc[im][jn][1] + bb.y;
            o1.x = acc[im][jn][2] + bb.x;
            o1.y = acc[im][jn][3] + bb.y;
            *reinterpret_cast<float2*>(&out[(size_t)r0 * V_N + col])       = o0;
            *reinterpret_cast<float2*>(&out[(size_t)(r0 + 8) * V_N + col]) = o1;
        }
    }
}

// ---------------------------------------------------------------------------
// Launch
// ---------------------------------------------------------------------------
extern "C" void kernel_launch(void* const* d_in, const int* in_sizes, int n_in,
                              void* d_out, int out_size)
{
    const int*   tokens = (const int*)d_in[0];     // (T, B) int32
    const float* emb    = (const float*)d_in[1];   // (V, E)
    const float* W1     = (const float*)d_in[2];   // (K*E, H)
    const float* b1     = (const float*)d_in[3];   // (H,)
    const float* Wout   = (const float*)d_in[4];   // (H, V)
    const float* bout   = (const float*)d_in[5];   // (V,)
    float*       out    = (float*)d_out;           // (T, B, V) fp32

    __half *hh, *wo, *eh, *el, *w1;
    cudaGetSymbolAddress((void**)&hh, g_hh);
    cudaGetSymbolAddress((void**)&wo, g_wo);
    cudaGetSymbolAddress((void**)&eh, g_eh);
    cudaGetSymbolAddress((void**)&el, g_el);
    cudaGetSymbolAddress((void**)&w1, g_w1);

    // Prepasses
    emb_split<<<(int)(((size_t)V_N * E_N) / 1024), 256>>>(emb);
    transpose_f16<<<dim3(H_N / 32, K1_N / 32), 256>>>(W1, w1, K1_N, H_N);
    transpose_f16<<<dim3(V_N / 32, H_N / 32), 256>>>(Wout, wo, H_N, V_N);

    // GEMM1 (fp16 2-product, gathered A) -> h fp16
    cudaFuncSetAttribute(kgram_gemm1_mma, cudaFuncAttributeMaxDynamicSharedMemorySize, G1_SMEM);
    kgram_gemm1_mma<<<dim3(M_N / 128, H_N / 256), 512, G1_SMEM>>>(tokens, eh, el, w1, b1);

    // GEMM2 (fp16 1-product)
    cudaFuncSetAttribute(kgram_gemm2_mma, cudaFuncAttributeMaxDynamicSharedMemorySize, G2_SMEM);
    kgram_gemm2_mma<<<dim3(M_N / 128, V_N / 256), 512, G2_SMEM>>>(hh, wo, bout, out);
}

// round 12
// speedup vs baseline: 4.1829x; 1.0722x over previous
#include <cuda_runtime.h>
#include <cuda_fp16.h>
#include <cstdint>
#include <math.h>

// Problem constants (KGramMLPSeqModel: T=1024, B=4, V=32000, E=1024, K=3, H=2048)
#define T_N   1024
#define B_N   4
#define V_N   32000
#define E_N   1024
#define KCTX  3
#define H_N   2048
#define M_N   (T_N * B_N)      // 4096
#define K1_N  (KCTX * E_N)     // 3072

// ---------------------------------------------------------------------------
// Device scratch (__device__ globals per allocation-free rule)
// ---------------------------------------------------------------------------
__device__ __half g_hh[(size_t)M_N * H_N];    // h fp16 (M,H) K-major
__device__ __half g_wo[(size_t)V_N * H_N];    // Wout^T fp16 (V,H) K-major
__device__ __half g_ef[(size_t)V_N * E_N];    // embedding fp16 (V,E)
__device__ __half g_w1[(size_t)H_N * K1_N];   // W1^T fp16 (H,K1) K-major

// ---------------------------------------------------------------------------
// Helpers (baseline PTX only: plain compute_103 target)
// ---------------------------------------------------------------------------
__device__ __forceinline__ uint32_t smem_u32(const void* p) {
    uint32_t a;
    asm("{ .reg .u64 t; cvta.to.shared.u64 t, %1; cvt.u32.u64 %0, t; }" : "=r"(a) : "l"(p));
    return a;
}
#define CP16(dst, src) \
    asm volatile("cp.async.cg.shared.global [%0], [%1], 16;" :: "r"(dst), "l"(src) : "memory")
#define CP_COMMIT() asm volatile("cp.async.commit_group;" ::: "memory")
#define CP_WAIT1()  asm volatile("cp.async.wait_group 1;" ::: "memory")

#define LDSM4(r, addr) \
    asm volatile("ldmatrix.sync.aligned.m8n8.x4.shared.b16 {%0,%1,%2,%3}, [%4];" \
        : "=r"((r)[0]), "=r"((r)[1]), "=r"((r)[2]), "=r"((r)[3]) : "r"(addr))

#define MMA16816(d, a, b0, b1) \
    asm volatile("mma.sync.aligned.m16n8k16.row.col.f32.f16.f16.f32 " \
        "{%0,%1,%2,%3}, {%4,%5,%6,%7}, {%8,%9}, {%0,%1,%2,%3};" \
        : "+f"((d)[0]), "+f"((d)[1]), "+f"((d)[2]), "+f"((d)[3]) \
        : "r"((a)[0]), "r"((a)[1]), "r"((a)[2]), "r"((a)[3]), "r"(b0), "r"(b1))

// ---------------------------------------------------------------------------
// Prepass A: embedding fp32 -> fp16, same layout
// ---------------------------------------------------------------------------
__global__ __launch_bounds__(256)
void emb_convert(const float* __restrict__ emb)
{
    const size_t i4 = ((size_t)blockIdx.x * 256 + threadIdx.x) * 4;
    const float4 v = *reinterpret_cast<const float4*>(emb + i4);
    __half2* o = reinterpret_cast<__half2*>(g_ef + i4);
    o[0] = __half2(__float2half_rn(v.x), __float2half_rn(v.y));
    o[1] = __half2(__float2half_rn(v.z), __float2half_rn(v.w));
}

// ---------------------------------------------------------------------------
// Prepass B: transpose to fp16: in (R, C) fp32 -> out (C, R) fp16
// ---------------------------------------------------------------------------
__global__ __launch_bounds__(256)
void transpose_f16(const float* __restrict__ in,
                   __half* __restrict__ o,
                   int R, int C)
{
    __shared__ float tile[32][33];
    const int tx = threadIdx.x & 31;
    const int ty = threadIdx.x >> 5;          // 0..7
    const int cBase = blockIdx.x * 32;
    const int rBase = blockIdx.y * 32;

    #pragma unroll
    for (int j = 0; j < 4; j++)
        tile[ty + j * 8][tx] = in[(size_t)(rBase + ty + j * 8) * C + cBase + tx];
    __syncthreads();
    #pragma unroll
    for (int j = 0; j < 4; j++) {
        const int n = cBase + ty + j * 8;
        const int k = rBase + tx;
        o[(size_t)n * R + k] = __float2half_rn(tile[tx][ty + j * 8]);
    }
}

// ---------------------------------------------------------------------------
// Shared GEMM geometry: BM=128, BN=256, BK=32; 512 threads, 16 warps (2Mx8N),
// warp tile 64x32; ROWB=80 conflict-free ldmatrix; 3-stage cp.async.
// Both GEMMs single-product fp16. Stage layout: A | B.
// ---------------------------------------------------------------------------
#define ROWB      80
#define A_BYTES   (128 * ROWB)     // 10240
#define B_BYTES   (256 * ROWB)     // 20480
#define OFF_A     0
#define OFF_B     A_BYTES
#define STAGE_B   (A_BYTES + B_BYTES)   // 30720
#define NSTAGE    3
#define GEMM_SMEM (NSTAGE * STAGE_B)    // 92160

// One 32-k chunk, warp tile 64x32 (acc[4][4][4]); single product.
#define COMPUTE_CHUNK(stb)                                                          \
    do {                                                                            \
        _Pragma("unroll")                                                           \
        for (int kk = 0; kk < 2; kk++) {                                            \
            const uint32_t colb = cselB + kk * 32;                                  \
            uint32_t af[4][4];                                                      \
            _Pragma("unroll")                                                       \
            for (int im = 0; im < 4; im++) {                                        \
                const uint32_t a = (stb) + OFF_A + (wm * 64 + im * 16 + rsel) * ROWB + colb; \
                LDSM4(af[im], a);                                                   \
            }                                                                       \
            uint32_t bf[2][4];                                                      \
            _Pragma("unroll")                                                       \
            for (int in = 0; in < 2; in++) {                                        \
                const uint32_t a = (stb) + OFF_B + (wn * 32 + in * 16 + rsel) * ROWB + colb; \
                LDSM4(bf[in], a);                                                   \
            }                                                                       \
            _Pragma("unroll")                                                       \
            for (int im = 0; im < 4; im++)                                          \
                _Pragma("unroll")                                                   \
                for (int jn = 0; jn < 4; jn++)                                      \
                    MMA16816(acc[im][jn], af[im], bf[jn >> 1][jn & 1], bf[jn >> 1][(jn & 1) + 2]); \
        }                                                                           \
    } while (0)

// ============================================================================
// GEMM1: h = silu(gather(emb) @ W1 + b1) -> fp16.  96 chunks.
// ============================================================================
#define G1_NCHUNK (K1_N / 32)   // 96

__global__ __launch_bounds__(512, 1)
void kgram_gemm1_mma(const int* __restrict__ tokens,
                     const __half* __restrict__ ef,
                     const __half* __restrict__ w1,
                     const float* __restrict__ b1)
{
    extern __shared__ char smem[];
    const uint32_t sb = smem_u32(smem);
    const int tid  = threadIdx.x;
    const int wid  = tid >> 5;
    const int lane = tid & 31;
    const int wm   = wid >> 3;          // 0..1 (M)
    const int wn   = wid & 7;           // 0..7 (N), 32 cols each

    const int rowBase = blockIdx.x * 128;
    const int colBase = blockIdx.y * 256;

    float acc[4][4][4];
    #pragma unroll
    for (int i = 0; i < 4; i++)
        #pragma unroll
        for (int j = 0; j < 4; j++)
            #pragma unroll
            for (int e = 0; e < 4; e++) acc[i][j][e] = 0.f;

    const int ldRow0 = tid >> 2;        // 0..127
    const int ldSeg  = tid & 3;
    const int ldCol  = ldSeg * 16;

    auto load_stage = [&](int c) {
        const int c0 = c * 32;
        const uint32_t stb = sb + (c % NSTAGE) * STAGE_B;
        const int kidx = c0 + ldSeg * 8;
        const int slot = kidx >> 10;
        const int off  = kidx & 1023;
        // A: gathered embedding row (128 rows); 1 row per thread
        {
            const int r = rowBase + ldRow0;
            const int t = r >> 2;
            const int b = r & 3;
            const int tt = t - KCTX + slot;
            int tok = 0;
            if (tt >= 0) tok = tokens[tt * B_N + b];
            if (tok < 0) tok = 0;
            if (tok >= V_N) tok = V_N - 1;
            const size_t gA = (size_t)tok * E_N + off;
            CP16(stb + ldRow0 * ROWB + ldCol + OFF_A, ef + gA);
        }
        // B: W1^T (256 rows); 2 rows per thread
        #pragma unroll
        for (int it = 0; it < 2; it++) {
            const int row = ldRow0 + it * 128;
            const size_t gB = (size_t)(colBase + row) * K1_N + c0 + ldSeg * 8;
            CP16(stb + row * ROWB + ldCol + OFF_B, w1 + gB);
        }
    };

    load_stage(0); CP_COMMIT();
    load_stage(1); CP_COMMIT();

    const int rsel  = lane & 15;
    const int cselB = (lane >> 4) * 16;

    for (int c = 0; c < G1_NCHUNK; c++) {
        CP_WAIT1();
        __syncthreads();
        if (c + 2 < G1_NCHUNK) load_stage(c + 2);
        CP_COMMIT();
        const uint32_t stb = sb + (c % NSTAGE) * STAGE_B;
        COMPUTE_CHUNK(stb);
    }

    // Epilogue: +b1, silu -> g_hh (fp16)
    const int mw = rowBase + wm * 64;
    const int nw = colBase + wn * 32;
    #pragma unroll
    for (int im = 0; im < 4; im++) {
        const int r0 = mw + im * 16 + (lane >> 2);
        #pragma unroll
        for (int jn = 0; jn < 4; jn++) {
            const int col = nw + jn * 8 + (lane & 3) * 2;
            const float2 bb = *reinterpret_cast<const float2*>(&b1[col]);
            float v00 = acc[im][jn][0] + bb.x;
            float v01 = acc[im][jn][1] + bb.y;
            float v10 = acc[im][jn][2] + bb.x;
            float v11 = acc[im][jn][3] + bb.y;
            v00 = v00 / (1.f + expf(-v00));
            v01 = v01 / (1.f + expf(-v01));
            v10 = v10 / (1.f + expf(-v10));
            v11 = v11 / (1.f + expf(-v11));
            *reinterpret_cast<__half2*>(g_hh + (size_t)r0 * H_N + col) =
                __half2(__float2half_rn(v00), __float2half_rn(v01));
            *reinterpret_cast<__half2*>(g_hh + (size_t)(r0 + 8) * H_N + col) =
                __half2(__float2half_rn(v10), __float2half_rn(v11));
        }
    }
}

// ============================================================================
// GEMM2: logits = h @ Wout + bout.  64 chunks.
// ============================================================================
#define G2_NCHUNK (H_N / 32)    // 64

__global__ __launch_bounds__(512, 1)
void kgram_gemm2_mma(const __half* __restrict__ hh,
                     const __half* __restrict__ wo,
                     const float* __restrict__ bout,
                     float* __restrict__ out)
{
    extern __shared__ char smem[];
    const uint32_t sb = smem_u32(smem);
    const int tid  = threadIdx.x;
    const int wid  = tid >> 5;
    const int lane = tid & 31;
    const int wm   = wid >> 3;          // 0..1
    const int wn   = wid & 7;           // 0..7

    const int rowBase = blockIdx.x * 128;   // M fastest -> B-strip reuse in L2
    const int colBase = blockIdx.y * 256;

    float acc[4][4][4];
    #pragma unroll
    for (int i = 0; i < 4; i++)
        #pragma unroll
        for (int j = 0; j < 4; j++)
            #pragma unroll
            for (int e = 0; e < 4; e++) acc[i][j][e] = 0.f;

    const int ldRow0 = tid >> 2;        // 0..127
    const int ldCol  = (tid & 3) * 16;
    const int kOff0  = ldCol >> 1;

    // Precomputed per-thread global base offsets (advance by +c*32 per chunk)
    const size_t baseA  = (size_t)(rowBase + ldRow0)       * H_N + kOff0;
    const size_t baseB0 = (size_t)(colBase + ldRow0)       * H_N + kOff0;
    const size_t baseB1 = (size_t)(colBase + ldRow0 + 128) * H_N + kOff0;
    const uint32_t dR0 = ldRow0 * ROWB + ldCol;
    const uint32_t dR1 = (ldRow0 + 128) * ROWB + ldCol;

    auto load_stage = [&](int c) {
        const int c0 = c * 32;
        const uint32_t stb = sb + (c % NSTAGE) * STAGE_B;
        CP16(stb + dR0 + OFF_A, hh + baseA + c0);
        CP16(stb + dR0 + OFF_B, wo + baseB0 + c0);
        CP16(stb + dR1 + OFF_B, wo + baseB1 + c0);
    };

    load_stage(0); CP_COMMIT();
    load_stage(1); CP_COMMIT();

    const int rsel  = lane & 15;
    const int cselB = (lane >> 4) * 16;

    for (int c = 0; c < G2_NCHUNK; c++) {
        CP_WAIT1();
        __syncthreads();
        if (c + 2 < G2_NCHUNK) load_stage(c + 2);
        CP_COMMIT();
        const uint32_t stb = sb + (c % NSTAGE) * STAGE_B;
        COMPUTE_CHUNK(stb);
    }

    // Epilogue: +bout -> gmem
    const int mw = rowBase + wm * 64;
    const int nw = colBase + wn * 32;
    #pragma unroll
    for (int im = 0; im < 4; im++) {
        const int r0 = mw + im * 16 + (lane >> 2);
        #pragma unroll
        for (int jn = 0; jn < 4; jn++) {
            const int col = nw + jn * 8 + (lane & 3) * 2;
            const float2 bb = *reinterpret_cast<const float2*>(&bout[col]);
            float2 o0, o1;
            o0.x = acc[im][jn][0] + bb.x;
            o0.y = acc[im][jn][1] + bb.y;
            o1.x = acc[im][jn][2] + bb.x;
            o1.y = acc[im][jn][3] + bb.y;
            *reinterpret_cast<float2*>(&out[(size_t)r0 * V_N + col])       = o0;
            *reinterpret_cast<float2*>(&out[(size_t)(r0 + 8) * V_N + col]) = o1;
        }
    }
}

// ---------------------------------------------------------------------------
// Launch
// ---------------------------------------------------------------------------
extern "C" void kernel_launch(void* const* d_in, const int* in_sizes, int n_in,
                              void* d_out, int out_size)
{
    const int*   tokens = (const int*)d_in[0];     // (T, B) int32
    const float* emb    = (const float*)d_in[1];   // (V, E)
    const float* W1     = (const float*)d_in[2];   // (K*E, H)
    const float* b1     = (const float*)d_in[3];   // (H,)
    const float* Wout   = (const float*)d_in[4];   // (H, V)
    const float* bout   = (const float*)d_in[5];   // (V,)
    float*       out    = (float*)d_out;           // (T, B, V) fp32

    __half *hh, *wo, *ef, *w1;
    cudaGetSymbolAddress((void**)&hh, g_hh);
    cudaGetSymbolAddress((void**)&wo, g_wo);
    cudaGetSymbolAddress((void**)&ef, g_ef);
    cudaGetSymbolAddress((void**)&w1, g_w1);

    // Prepasses
    emb_convert<<<(int)(((size_t)V_N * E_N) / 1024), 256>>>(emb);
    transpose_f16<<<dim3(H_N / 32, K1_N / 32), 256>>>(W1, w1, K1_N, H_N);
    transpose_f16<<<dim3(V_N / 32, H_N / 32), 256>>>(Wout, wo, H_N, V_N);

    // GEMM1 (fp16 1-product, gathered A) -> h fp16
    cudaFuncSetAttribute(kgram_gemm1_mma, cudaFuncAttributeMaxDynamicSharedMemorySize, GEMM_SMEM);
    kgram_gemm1_mma<<<dim3(M_N / 128, H_N / 256), 512, GEMM_SMEM>>>(tokens, ef, w1, b1);

    // GEMM2 (fp16 1-product)
    cudaFuncSetAttribute(kgram_gemm2_mma, cudaFuncAttributeMaxDynamicSharedMemorySize, GEMM_SMEM);
    kgram_gemm2_mma<<<dim3(M_N / 128, V_N / 256), 512, GEMM_SMEM>>>(hh, wo, bout, out);
}